// round 10
// baseline (speedup 1.0000x reference)
#include <cuda_runtime.h>
#include <cuda_fp16.h>
#include <cstdint>

// ---------------- problem constants ----------------
#define NNODES   20000
#define FEAT     500
#define HID      256
#define LAT      64
#define NPRED    5
#define NCLS     16
#define NODE_LEN (NNODES + NNODES * NPRED)      // 120000
#define GENF     (NPRED * FEAT)                 // 2500
#define FC1N     256
#define FC2N     2048

#define OUT_GEN_OFF ((long long)NNODES)
#define OUT_NC_OFF  ((long long)NNODES + (long long)NNODES * GENF)

// ---------------- scratch (static device globals; no allocation) ------------
__device__ float g_bufA[(size_t)NODE_LEN * HID];
__device__ float g_bufB[(size_t)NNODES * HID];
__device__ float g_z[(size_t)NNODES * LAT];
__device__ float g_c7[(size_t)NODE_LEN * NCLS];
__device__ int   g_pdeg[NNODES];
__device__ int   g_is64;
// fp16 operands
__device__ __half g_g1h[(size_t)NNODES * FC1N];
__device__ __half g_g2h[(size_t)NNODES * FC2N];
__device__ __half g_fillh[(size_t)NODE_LEN * 512];
__device__ __half g_fhi[(size_t)NNODES * 512];
__device__ __half g_flo[(size_t)NNODES * 512];
__device__ __half g_znh[(size_t)NNODES * LAT];
__device__ __half g_wh_fc2[(size_t)2048 * 256];
__device__ __half g_wh_flat[(size_t)2560 * 2048];
__device__ __half g_wh_gc3[(size_t)256 * 512];
__device__ __half g_wh_fc1[(size_t)256 * 64];
__device__ __half g_whi_gc1[(size_t)256 * 512];
__device__ __half g_wlo_gc1[(size_t)256 * 512];
// CSR scratch
__device__ int   g_cnt[NODE_LEN];
__device__ int   g_fill[NODE_LEN];
__device__ int   g_off_enc[NNODES + 1];
__device__ int   g_off_mend[NODE_LEN + 1];
__device__ int   g_ecol[700000];
__device__ float g_eval[700000];
__device__ int   g_mcol[900000];

// ---------------- helpers ----------------
__device__ __forceinline__ uint32_t smem_u32(const void* p) {
    uint32_t a;
    asm("{ .reg .u64 t; cvta.to.shared.u64 t, %1; cvt.u32.u64 %0, t; }" : "=r"(a) : "l"(p));
    return a;
}
__device__ __forceinline__ void ldsm_x4(uint32_t addr, uint32_t* r) {
    asm volatile("ldmatrix.sync.aligned.m8n8.x4.shared.b16 {%0,%1,%2,%3}, [%4];"
                 : "=r"(r[0]), "=r"(r[1]), "=r"(r[2]), "=r"(r[3]) : "r"(addr));
}
__device__ __forceinline__ void mma_f16(float* c, const uint32_t* a, uint32_t b0, uint32_t b1) {
    asm volatile(
        "mma.sync.aligned.m16n8k16.row.col.f32.f16.f16.f32 "
        "{%0,%1,%2,%3}, {%4,%5,%6,%7}, {%8,%9}, {%0,%1,%2,%3};"
        : "+f"(c[0]), "+f"(c[1]), "+f"(c[2]), "+f"(c[3])
        : "r"(a[0]), "r"(a[1]), "r"(a[2]), "r"(a[3]), "r"(b0), "r"(b1));
}
#define CP_ASYNC16(dst, src) \
    asm volatile("cp.async.cg.shared.global [%0], [%1], 16;" :: "r"(dst), "l"(src))
#define CP_COMMIT() asm volatile("cp.async.commit_group;" ::: "memory")
#define CP_WAIT(n)  asm volatile("cp.async.wait_group %0;" :: "n"(n) : "memory")

// ---------------- index dtype detection ----------------
__global__ void detect_idx_kernel(const void* adj_rows) {
    int lane = threadIdx.x;
    const long long* p = (const long long*)adj_rows;
    int bad = 0;
    for (int i = lane; i < 256; i += 32) {
        long long v = p[i];
        if (v < 0 || v >= NODE_LEN) bad = 1;
    }
    unsigned m = __ballot_sync(0xffffffffu, bad);
    if (lane == 0) g_is64 = (m == 0) ? 1 : 0;
}
__device__ __forceinline__ long long load_idx(const void* p, long long i) {
    return g_is64 ? ((const long long*)p)[i] : (long long)((const int*)p)[i];
}

// ---------------- CSR build ----------------
__global__ void enc_hist_kernel(const void* __restrict__ rows, long long nnz) {
    long long e = (long long)blockIdx.x * blockDim.x + threadIdx.x;
    if (e >= nnz) return;
    atomicAdd(&g_cnt[load_idx(rows, e)], 1);
}
__global__ void enc_fill_kernel(const void* __restrict__ rows, const void* __restrict__ cols,
                                const float* __restrict__ vals, long long nnz) {
    long long e = (long long)blockIdx.x * blockDim.x + threadIdx.x;
    if (e >= nnz) return;
    int r = (int)load_idx(rows, e);
    int pos = atomicAdd(&g_fill[r], 1);
    g_ecol[pos] = (int)load_idx(cols, e);
    g_eval[pos] = vals[e];
}
__global__ void scan_kernel(const int* __restrict__ cnt, int* __restrict__ off,
                            int* __restrict__ fill, int n) {
    __shared__ int part[1024];
    int t = threadIdx.x;
    int chunk = (n + 1023) >> 10;
    int lo = t * chunk, hi = lo + chunk;
    if (hi > n) hi = n;
    int s = 0;
    for (int i = lo; i < hi; i++) s += cnt[i];
    part[t] = s;
    __syncthreads();
    for (int d = 1; d < 1024; d <<= 1) {
        int add = (t >= d) ? part[t - d] : 0;
        __syncthreads();
        part[t] += add;
        __syncthreads();
    }
    int run = part[t] - s;
    for (int i = lo; i < hi; i++) {
        off[i] = run; fill[i] = run;
        run += cnt[i];
    }
    if (t == 1023) off[n] = part[1023];
}
__global__ void mend_hist_edges_kernel(const void* __restrict__ edges, int E) {
    int e = blockIdx.x * blockDim.x + threadIdx.x;
    if (e >= E) return;
    int lo = (int)load_idx(edges, 2LL * e);
    int hi = (int)load_idx(edges, 2LL * e + 1);
    atomicAdd(&g_cnt[lo], 1);
    atomicAdd(&g_cnt[hi], 1);
}
__global__ void mend_hist_new_kernel(const int* __restrict__ pdeg) {
    int t = blockIdx.x * blockDim.x + threadIdx.x;
    if (t >= NNODES * NPRED) return;
    int node = t / NPRED, j = t - node * NPRED;
    if (j < pdeg[node]) {
        atomicAdd(&g_cnt[node], 1);
        g_cnt[NNODES + t] = 1;
    }
}
__global__ void mend_fill_edges_kernel(const void* __restrict__ edges, int E) {
    int e = blockIdx.x * blockDim.x + threadIdx.x;
    if (e >= E) return;
    int lo = (int)load_idx(edges, 2LL * e);
    int hi = (int)load_idx(edges, 2LL * e + 1);
    int p0 = atomicAdd(&g_fill[lo], 1);
    g_mcol[p0] = hi;
    int p1 = atomicAdd(&g_fill[hi], 1);
    g_mcol[p1] = lo;
}
__global__ void mend_fill_new_kernel(const int* __restrict__ pdeg) {
    int t = blockIdx.x * blockDim.x + threadIdx.x;
    if (t >= NNODES * NPRED) return;
    int node = t / NPRED, j = t - node * NPRED;
    if (j < pdeg[node]) {
        int p0 = atomicAdd(&g_fill[node], 1);
        g_mcol[p0] = NNODES + t;
        g_mcol[g_off_mend[NNODES + t]] = node;
    }
}

// ---------------- gather SpMM (warp per row) ----------------
template <int D, bool MEND>
__global__ void spmm_gather_kernel(const int* __restrict__ off, const int* __restrict__ cols,
                                   const float* __restrict__ vals,
                                   const float* __restrict__ x, const float* __restrict__ bias,
                                   float* __restrict__ y, int nrows)
{
    int w = (int)(((long long)blockIdx.x * blockDim.x + threadIdx.x) >> 5);
    int lane = threadIdx.x & 31;
    if (w >= nrows) return;
    int e0 = off[w], e1 = off[w + 1];

    if (D == 256) {
        float a[8] = {0, 0, 0, 0, 0, 0, 0, 0};
        const int cb = lane * 4;
        for (int e = e0; e < e1; e++) {
            long long c = cols[e];
            float4 t0 = *(const float4*)(x + c * 256 + cb);
            float4 t1 = *(const float4*)(x + c * 256 + 128 + cb);
            float v = vals[e];
            a[0] += v * t0.x; a[1] += v * t0.y; a[2] += v * t0.z; a[3] += v * t0.w;
            a[4] += v * t1.x; a[5] += v * t1.y; a[6] += v * t1.z; a[7] += v * t1.w;
        }
        float4 o0, o1;
        o0.x = fmaxf(a[0] + bias[cb + 0], 0.f);
        o0.y = fmaxf(a[1] + bias[cb + 1], 0.f);
        o0.z = fmaxf(a[2] + bias[cb + 2], 0.f);
        o0.w = fmaxf(a[3] + bias[cb + 3], 0.f);
        o1.x = fmaxf(a[4] + bias[128 + cb + 0], 0.f);
        o1.y = fmaxf(a[5] + bias[128 + cb + 1], 0.f);
        o1.z = fmaxf(a[6] + bias[128 + cb + 2], 0.f);
        o1.w = fmaxf(a[7] + bias[128 + cb + 3], 0.f);
        *(float4*)(y + (long long)w * 256 + cb) = o0;
        *(float4*)(y + (long long)w * 256 + 128 + cb) = o1;
    } else if (D == 64) {
        float a0 = 0.f, a1 = 0.f;
        const int cb = lane * 2;
        for (int e = e0; e < e1; e++) {
            long long c = cols[e];
            float2 t = *(const float2*)(x + c * 64 + cb);
            float v = vals[e];
            a0 += v * t.x; a1 += v * t.y;
        }
        float2 o;
        o.x = fmaxf(a0 + bias[cb + 0], 0.f);
        o.y = fmaxf(a1 + bias[cb + 1], 0.f);
        *(float2*)(y + (long long)w * 64 + cb) = o;
    } else {  // D == 16, MEND
        if (lane < 16) {
            float a = 0.f;
            for (int e = e0; e < e1; e++)
                a += x[(long long)cols[e] * 16 + lane];
            float inv = 1.0f / (1.0f + (float)(e1 - e0));
            float v = (a + x[(long long)w * 16 + lane]) * inv + bias[lane];
            y[(long long)w * 16 + lane] = fmaxf(v, 0.f);
        }
    }
}

// mend layer1 gather (D=256) fused with gc4 skinny GEMM: writes c7[r][0..15]
__global__ void __launch_bounds__(256) mend_gather_gc4_kernel(
    const int* __restrict__ off, const int* __restrict__ cols,
    const float* __restrict__ x, const float* __restrict__ bias,
    const float* __restrict__ Wgc4, float* __restrict__ c7, int nrows)
{
    __shared__ float Ws[256 * 16];
    for (int i = threadIdx.x; i < 256 * 16; i += 256) Ws[i] = Wgc4[i];
    __syncthreads();
    int w = (int)(((long long)blockIdx.x * blockDim.x + threadIdx.x) >> 5);
    int lane = threadIdx.x & 31;
    if (w >= nrows) return;
    int e0 = off[w], e1 = off[w + 1];

    float a[8] = {0, 0, 0, 0, 0, 0, 0, 0};
    const int cb = lane * 4;
    for (int e = e0; e < e1; e++) {
        long long c = cols[e];
        float4 t0 = *(const float4*)(x + c * 256 + cb);
        float4 t1 = *(const float4*)(x + c * 256 + 128 + cb);
        a[0] += t0.x; a[1] += t0.y; a[2] += t0.z; a[3] += t0.w;
        a[4] += t1.x; a[5] += t1.y; a[6] += t1.z; a[7] += t1.w;
    }
    float h2[8];
    {
        float inv = 1.0f / (1.0f + (float)(e1 - e0));
        const float* xr = x + (long long)w * 256;
#pragma unroll
        for (int j = 0; j < 4; j++) {
            h2[j]     = fmaxf((a[j]     + xr[cb + j])       * inv + bias[cb + j], 0.f);
            h2[4 + j] = fmaxf((a[4 + j] + xr[128 + cb + j]) * inv + bias[128 + cb + j], 0.f);
        }
    }
    float part[16];
#pragma unroll
    for (int q = 0; q < 16; q++) part[q] = 0.f;
#pragma unroll
    for (int j = 0; j < 4; j++) {
        int k0 = cb + j, k1 = 128 + cb + j;
#pragma unroll
        for (int q = 0; q < 16; q++)
            part[q] += h2[j] * Ws[k0 * 16 + q] + h2[4 + j] * Ws[k1 * 16 + q];
    }
#pragma unroll
    for (int o = 16; o; o >>= 1)
#pragma unroll
        for (int q = 0; q < 16; q++)
            part[q] += __shfl_xor_sync(0xffffffffu, part[q], o);
    if (lane == 0) {
        float* co = c7 + (long long)w * 16;
#pragma unroll
        for (int q = 0; q < 16; q += 4)
            *(float4*)(co + q) = make_float4(part[q], part[q + 1], part[q + 2], part[q + 3]);
    }
}

// ---------------- prep kernels ----------------
__global__ void transpose_half_kernel(const float* __restrict__ W, __half* __restrict__ WT,
                                      int K, int N, int Kpad, int Npad) {
    __shared__ float tile[32][33];
    int kb = blockIdx.x * 32, nb = blockIdx.y * 32;
    int tx = threadIdx.x, ty = threadIdx.y;   // 32 x 8
#pragma unroll
    for (int i = 0; i < 4; i++) {
        int k = kb + ty + i * 8, n = nb + tx;
        tile[ty + i * 8][tx] = (k < K && n < N) ? W[(long long)k * N + n] : 0.0f;
    }
    __syncthreads();
#pragma unroll
    for (int i = 0; i < 4; i++) {
        int n = nb + ty + i * 8, k = kb + tx;
        if (n < Npad && k < Kpad)
            WT[(long long)n * Kpad + k] = __float2half_rn(tile[tx][ty + i * 8]);
    }
}
// split transpose: W -> WThi + WTlo  (hi = rn(half), lo = rn(half(v - hi)))
__global__ void transpose_half_split_kernel(const float* __restrict__ W,
                                            __half* __restrict__ WThi, __half* __restrict__ WTlo,
                                            int K, int N, int Kpad, int Npad) {
    __shared__ float tile[32][33];
    int kb = blockIdx.x * 32, nb = blockIdx.y * 32;
    int tx = threadIdx.x, ty = threadIdx.y;
#pragma unroll
    for (int i = 0; i < 4; i++) {
        int k = kb + ty + i * 8, n = nb + tx;
        tile[ty + i * 8][tx] = (k < K && n < N) ? W[(long long)k * N + n] : 0.0f;
    }
    __syncthreads();
#pragma unroll
    for (int i = 0; i < 4; i++) {
        int n = nb + ty + i * 8, k = kb + tx;
        if (n < Npad && k < Kpad) {
            float v = tile[tx][ty + i * 8];
            __half h = __float2half_rn(v);
            WThi[(long long)n * Kpad + k] = h;
            WTlo[(long long)n * Kpad + k] = __float2half_rn(v - __half2float(h));
        }
    }
}
// feat -> fhi/flo [NNODES x 512] and fillh rows [0, NNODES)
__global__ void feat_prep_kernel(const float* __restrict__ feat,
                                 __half* __restrict__ fhi, __half* __restrict__ flo,
                                 __half* __restrict__ fillh) {
    long long i = (long long)blockIdx.x * blockDim.x + threadIdx.x;
    if (i >= (long long)NNODES * 512) return;
    int r = (int)(i >> 9), c = (int)(i & 511);
    float v = (c < FEAT) ? feat[(long long)r * FEAT + c] : 0.0f;
    __half h = __float2half_rn(v);
    fhi[i] = h;
    flo[i] = __float2half_rn(v - __half2float(h));
    fillh[i] = h;
}
// znh = half(z + noise)
__global__ void add_half_kernel(__half* __restrict__ o, const float* __restrict__ a,
                                const float* __restrict__ b, long long n)
{
    long long i = (long long)blockIdx.x * blockDim.x + threadIdx.x;
    if (i < n) o[i] = __float2half_rn(a[i] + b[i]);
}

// ---------------- fp16 mma GEMM ------------------
#define HSTAGES 4
#define H_STRIDE_B 80
#define H_MAT_BYTES (128 * H_STRIDE_B)          // 10240
#define H_STAGE_BYTES (2 * H_MAT_BYTES)         // 20480
#define H_SMEM_TOTAL (HSTAGES * H_STAGE_BYTES)  // 81920

// EPI: 0 none, 1 bias+relu, 2 bias+tanh.  OUT: 0 f32 C, 1 half Ch, 2 f32 C + genh->fillh
// ACC: accumulate into existing f32 C (OUT==0 only)
template <int EPI, int OUT, bool ACC>
__global__ void __launch_bounds__(256, 2) hmma_gemm_kernel(
    const __half* __restrict__ A, const __half* __restrict__ BT,
    const float* __restrict__ bias,
    float* __restrict__ C, __half* __restrict__ Ch,
    int M, int N, int K, int Kpad)
{
    extern __shared__ char smem[];
    const uint32_t sbase = smem_u32(smem);
    const int tid = threadIdx.x;
    const int wid = tid >> 5, lane = tid & 31;
    const int gid = lane >> 2, tig = lane & 3;
    const int warp_m = wid & 3, warp_n = wid >> 2;
    const int m0 = blockIdx.y * 128, n0 = blockIdx.x * 128;

    const int crow = tid >> 1;
    const int cboff = (tid & 1) * 32;

    const __half* aptr;
    {
        int r = m0 + crow;
        int rr = (r < M) ? r : (M - 1);
        aptr = A + (long long)rr * K;
    }
    const __half* bptr = BT + (long long)(n0 + crow) * Kpad;

    const uint32_t sA_wr = sbase + (uint32_t)crow * H_STRIDE_B + (uint32_t)cboff;
    const uint32_t sB_wr = sA_wr + H_MAT_BYTES;

    const int nChunks = K >> 5;

    auto issue = [&](int chunk) {
        int s = chunk & (HSTAGES - 1);
        uint32_t da = sA_wr + (uint32_t)s * H_STAGE_BYTES;
        uint32_t db = sB_wr + (uint32_t)s * H_STAGE_BYTES;
        const char* ga = (const char*)aptr + chunk * 64 + cboff;
        const char* gb = (const char*)bptr + chunk * 64 + cboff;
        CP_ASYNC16(da, ga); CP_ASYNC16(da + 16, ga + 16);
        CP_ASYNC16(db, gb); CP_ASYNC16(db + 16, gb + 16);
        CP_COMMIT();
    };

    float acc[2][8][4];
#pragma unroll
    for (int f = 0; f < 2; f++)
#pragma unroll
        for (int j = 0; j < 8; j++)
#pragma unroll
            for (int q = 0; q < 4; q++) acc[f][j][q] = 0.0f;

    int pro = (HSTAGES - 1 < nChunks) ? HSTAGES - 1 : nChunks;
    for (int s = 0; s < pro; s++) issue(s);
    for (int s = pro; s < HSTAGES - 1; s++) CP_COMMIT();

    uint32_t a_off[2];
#pragma unroll
    for (int f = 0; f < 2; f++) {
        uint32_t row = (uint32_t)(warp_m * 32 + f * 16 + (lane & 15));
        uint32_t colb = (uint32_t)((lane >> 4) << 4);
        a_off[f] = row * H_STRIDE_B + colb;
    }
    uint32_t b_off[4];
#pragma unroll
    for (int jp = 0; jp < 4; jp++) {
        uint32_t row = (uint32_t)(warp_n * 64 + jp * 16 + ((lane >> 4) << 3) + (lane & 7));
        uint32_t colb = (uint32_t)(((lane >> 3) & 1) << 4);
        b_off[jp] = row * H_STRIDE_B + colb;
    }

    for (int i = 0; i < nChunks; i++) {
        if (i + HSTAGES - 1 < nChunks) issue(i + HSTAGES - 1);
        else CP_COMMIT();
        CP_WAIT(HSTAGES - 1);
        __syncthreads();

        uint32_t sA = sbase + (uint32_t)(i & (HSTAGES - 1)) * H_STAGE_BYTES;
        uint32_t sB = sA + H_MAT_BYTES;
#pragma unroll
        for (int kk = 0; kk < 2; kk++) {
            uint32_t afr[2][4];
            ldsm_x4(sA + a_off[0] + kk * 32, afr[0]);
            ldsm_x4(sA + a_off[1] + kk * 32, afr[1]);
#pragma unroll
            for (int jp = 0; jp < 4; jp++) {
                uint32_t br[4];
                ldsm_x4(sB + b_off[jp] + kk * 32, br);
                mma_f16(acc[0][2 * jp + 0], afr[0], br[0], br[1]);
                mma_f16(acc[1][2 * jp + 0], afr[1], br[0], br[1]);
                mma_f16(acc[0][2 * jp + 1], afr[0], br[2], br[3]);
                mma_f16(acc[1][2 * jp + 1], afr[1], br[2], br[3]);
            }
        }
        __syncthreads();
    }

#pragma unroll
    for (int f = 0; f < 2; f++) {
#pragma unroll
        for (int rr = 0; rr < 2; rr++) {
            int r = m0 + warp_m * 32 + f * 16 + rr * 8 + gid;
            if (r >= M) continue;
#pragma unroll
            for (int j = 0; j < 8; j++) {
                int c = n0 + warp_n * 64 + j * 8 + tig * 2;
                if (c >= N) continue;
                float v0 = acc[f][j][rr * 2 + 0], v1 = acc[f][j][rr * 2 + 1];
                if (ACC) {
                    float2 old = *(const float2*)(C + (long long)r * N + c);
                    v0 += old.x; v1 += old.y;
                }
                if (EPI >= 1) { v0 += bias[c]; v1 += bias[c + 1]; }
                if (EPI == 1) { v0 = fmaxf(v0, 0.f); v1 = fmaxf(v1, 0.f); }
                if (EPI == 2) { v0 = tanhf(v0); v1 = tanhf(v1); }
                if (OUT == 0) {
                    *(float2*)(C + (long long)r * N + c) = make_float2(v0, v1);
                } else if (OUT == 1) {
                    *(__half2*)(Ch + (long long)r * N + c) = __floats2half2_rn(v0, v1);
                } else {
                    *(float2*)(C + (long long)r * N + c) = make_float2(v0, v1);
                    int j5 = c / FEAT, cc = c - j5 * FEAT;
                    *(__half2*)(Ch + ((size_t)(NNODES + r * NPRED + j5) * 512 + cc)) =
                        __floats2half2_rn(v0, v1);
                }
            }
        }
    }
}

// ---------------- SIMT SGEMM (precision-critical small GEMM: step 3) ----
#define BM 128
#define BN 128
#define BK 8
__global__ void __launch_bounds__(256, 2) sgemm_kernel(
    const float* __restrict__ A, const float* __restrict__ B,
    float* __restrict__ C, int M, int N, int K)
{
    __shared__ float As[BK][BM];
    __shared__ float Bs[BK][BN];
    const int tid = threadIdx.x;
    const int tx = tid & 15, ty = tid >> 4;
    const int rbase = blockIdx.y * BM, cbase = blockIdx.x * BN;
    float acc[8][8];
#pragma unroll
    for (int i = 0; i < 8; i++)
#pragma unroll
        for (int j = 0; j < 8; j++) acc[i][j] = 0.0f;
    const int arow = tid >> 1, acol = (tid & 1) * 4;
    const int brow = tid >> 5, bcol = (tid & 31) * 4;
    const float* arowptr = (rbase + arow < M) ? A + (long long)(rbase + arow) * K : nullptr;

    for (int kt = 0; kt < K; kt += BK) {
        float4 av = make_float4(0.f, 0.f, 0.f, 0.f);
        if (arowptr) {
            int kc = kt + acol;
            if (kc + 3 < K) av = *(const float4*)(arowptr + kc);
            else {
                if (kc + 0 < K) av.x = arowptr[kc + 0];
                if (kc + 1 < K) av.y = arowptr[kc + 1];
                if (kc + 2 < K) av.z = arowptr[kc + 2];
                if (kc + 3 < K) av.w = arowptr[kc + 3];
            }
        }
        As[acol + 0][arow] = av.x; As[acol + 1][arow] = av.y;
        As[acol + 2][arow] = av.z; As[acol + 3][arow] = av.w;
        float4 bv = make_float4(0.f, 0.f, 0.f, 0.f);
        {
            int kr = kt + brow, cc = cbase + bcol;
            if (kr < K) {
                const float* bp = B + (long long)kr * N + cc;
                if (cc + 3 < N) bv = *(const float4*)bp;
                else {
                    if (cc + 0 < N) bv.x = bp[0];
                    if (cc + 1 < N) bv.y = bp[1];
                    if (cc + 2 < N) bv.z = bp[2];
                    if (cc + 3 < N) bv.w = bp[3];
                }
            }
        }
        *(float4*)&Bs[brow][bcol] = bv;
        __syncthreads();
#pragma unroll
        for (int k = 0; k < BK; k++) {
            float ra[8], rb[8];
            *(float4*)&ra[0] = *(const float4*)&As[k][ty * 4];
            *(float4*)&ra[4] = *(const float4*)&As[k][64 + ty * 4];
            *(float4*)&rb[0] = *(const float4*)&Bs[k][tx * 4];
            *(float4*)&rb[4] = *(const float4*)&Bs[k][64 + tx * 4];
#pragma unroll
            for (int i = 0; i < 8; i++)
#pragma unroll
                for (int j = 0; j < 8; j++) acc[i][j] += ra[i] * rb[j];
        }
        __syncthreads();
    }
#pragma unroll
    for (int i = 0; i < 8; i++) {
        int r = rbase + ((i < 4) ? (ty * 4 + i) : (64 + ty * 4 + i - 4));
        if (r >= M) continue;
#pragma unroll
        for (int j = 0; j < 8; j++) {
            int c = cbase + ((j < 4) ? (tx * 4 + j) : (64 + tx * 4 + j - 4));
            if (c >= N) continue;
            C[(long long)r * N + c] = acc[i][j];
        }
    }
}

// ---------------- misc ----------------
__global__ void degree_kernel(const float* __restrict__ z, const float* __restrict__ Wr,
                              const float* __restrict__ br, float* __restrict__ deg_out,
                              int* __restrict__ pdeg, int n)
{
    int r = blockIdx.x * (blockDim.x >> 5) + (threadIdx.x >> 5);
    int lane = threadIdx.x & 31;
    if (r >= n) return;
    float s = z[(long long)r * LAT + lane] * Wr[lane]
            + z[(long long)r * LAT + 32 + lane] * Wr[32 + lane];
#pragma unroll
    for (int o = 16; o; o >>= 1) s += __shfl_xor_sync(0xffffffffu, s, o);
    if (lane == 0) {
        float d = fmaxf(s + br[0], 0.0f);
        deg_out[r] = d;
        int pi = (int)d;
        if (pi > NPRED) pi = NPRED;
        pdeg[r] = pi;
    }
}

// ---------------- host ----------------
static inline int cdiv(long long a, long long b) { return (int)((a + b - 1) / b); }

extern "C" void kernel_launch(void* const* d_in, const int* in_sizes, int n_in,
                              void* d_out, int out_size)
{
    const float* feat     = (const float*)d_in[0];
    const void*  edges    = d_in[1];
    const void*  adj_rows = d_in[2];
    const void*  adj_cols = d_in[3];
    const float* adj_vals = (const float*)d_in[4];
    const float* noise    = (const float*)d_in[5];
    const float* W_gc1 = (const float*)d_in[6];   const float* b_gc1 = (const float*)d_in[7];
    const float* W_gc2 = (const float*)d_in[8];   const float* b_gc2 = (const float*)d_in[9];
    const float* W_reg = (const float*)d_in[10];  const float* b_reg = (const float*)d_in[11];
    const float* W_fc1 = (const float*)d_in[12];  const float* b_fc1 = (const float*)d_in[13];
    const float* W_fc2 = (const float*)d_in[14];  const float* b_fc2 = (const float*)d_in[15];
    const float* W_flat = (const float*)d_in[16]; const float* b_flat = (const float*)d_in[17];
    const float* W_gc3 = (const float*)d_in[18];  const float* b_gc3 = (const float*)d_in[19];
    const float* W_gc4 = (const float*)d_in[20];  const float* b_gc4 = (const float*)d_in[21];

    float* out = (float*)d_out;
    float* out_deg = out;
    float* out_gen = out + OUT_GEN_OFF;
    float* out_nc  = out + OUT_NC_OFF;

    const long long nnz_adj = in_sizes[2];
    const int E = in_sizes[1] / 2;

    void* p;
    float *bufA, *bufB, *z, *c7;
    __half *g1h, *g2h, *fillh, *fhi, *flo, *znh;
    __half *wh_fc2, *wh_flat, *wh_gc3, *wh_fc1, *whi_gc1, *wlo_gc1;
    int *pdeg, *cnt, *fill, *off_enc, *off_mend, *ecol, *mcol;
    float *eval;
    cudaGetSymbolAddress(&p, g_bufA);  bufA  = (float*)p;
    cudaGetSymbolAddress(&p, g_bufB);  bufB  = (float*)p;
    cudaGetSymbolAddress(&p, g_z);     z     = (float*)p;
    cudaGetSymbolAddress(&p, g_c7);    c7    = (float*)p;
    cudaGetSymbolAddress(&p, g_pdeg);  pdeg  = (int*)p;
    cudaGetSymbolAddress(&p, g_cnt);   cnt   = (int*)p;
    cudaGetSymbolAddress(&p, g_fill);  fill  = (int*)p;
    cudaGetSymbolAddress(&p, g_off_enc);  off_enc  = (int*)p;
    cudaGetSymbolAddress(&p, g_off_mend); off_mend = (int*)p;
    cudaGetSymbolAddress(&p, g_ecol);  ecol  = (int*)p;
    cudaGetSymbolAddress(&p, g_eval);  eval  = (float*)p;
    cudaGetSymbolAddress(&p, g_mcol);  mcol  = (int*)p;
    cudaGetSymbolAddress(&p, g_g1h);   g1h   = (__half*)p;
    cudaGetSymbolAddress(&p, g_g2h);   g2h   = (__half*)p;
    cudaGetSymbolAddress(&p, g_fillh); fillh = (__half*)p;
    cudaGetSymbolAddress(&p, g_fhi);   fhi   = (__half*)p;
    cudaGetSymbolAddress(&p, g_flo);   flo   = (__half*)p;
    cudaGetSymbolAddress(&p, g_znh);   znh   = (__half*)p;
    cudaGetSymbolAddress(&p, g_wh_fc2);  wh_fc2  = (__half*)p;
    cudaGetSymbolAddress(&p, g_wh_flat); wh_flat = (__half*)p;
    cudaGetSymbolAddress(&p, g_wh_gc3);  wh_gc3  = (__half*)p;
    cudaGetSymbolAddress(&p, g_wh_fc1);  wh_fc1  = (__half*)p;
    cudaGetSymbolAddress(&p, g_whi_gc1); whi_gc1 = (__half*)p;
    cudaGetSymbolAddress(&p, g_wlo_gc1); wlo_gc1 = (__half*)p;

    cudaFuncSetAttribute((const void*)hmma_gemm_kernel<0, 0, false>,
                         cudaFuncAttributeMaxDynamicSharedMemorySize, H_SMEM_TOTAL);
    cudaFuncSetAttribute((const void*)hmma_gemm_kernel<0, 0, true>,
                         cudaFuncAttributeMaxDynamicSharedMemorySize, H_SMEM_TOTAL);
    cudaFuncSetAttribute((const void*)hmma_gemm_kernel<1, 1, false>,
                         cudaFuncAttributeMaxDynamicSharedMemorySize, H_SMEM_TOTAL);
    cudaFuncSetAttribute((const void*)hmma_gemm_kernel<2, 2, false>,
                         cudaFuncAttributeMaxDynamicSharedMemorySize, H_SMEM_TOTAL);

    const int TB = 256;
    dim3 tblk(32, 8);

    // 0) prep: idx detect, weight transposes, feat split, fillh
    detect_idx_kernel<<<1, 32>>>(adj_rows);
    transpose_half_kernel<<<dim3(cdiv(256, 32), cdiv(2048, 32)), tblk>>>(W_fc2, wh_fc2, 256, 2048, 256, 2048);
    transpose_half_kernel<<<dim3(cdiv(2048, 32), cdiv(2560, 32)), tblk>>>(W_flat, wh_flat, 2048, 2500, 2048, 2560);
    transpose_half_kernel<<<dim3(cdiv(512, 32), cdiv(256, 32)), tblk>>>(W_gc3, wh_gc3, 500, 256, 512, 256);
    transpose_half_kernel<<<dim3(cdiv(64, 32), cdiv(256, 32)), tblk>>>(W_fc1, wh_fc1, 64, 256, 64, 256);
    transpose_half_split_kernel<<<dim3(cdiv(512, 32), cdiv(256, 32)), tblk>>>(W_gc1, whi_gc1, wlo_gc1, 500, 256, 512, 256);
    feat_prep_kernel<<<cdiv((long long)NNODES * 512, TB), TB>>>(feat, fhi, flo, fillh);

    // 0b) encoder CSR build
    cudaMemsetAsync(cnt, 0, NNODES * sizeof(int));
    enc_hist_kernel<<<cdiv(nnz_adj, TB), TB>>>(adj_rows, nnz_adj);
    scan_kernel<<<1, 1024>>>(cnt, off_enc, fill, NNODES);
    enc_fill_kernel<<<cdiv(nnz_adj, TB), TB>>>(adj_rows, adj_cols, adj_vals, nnz_adj);

    // 1) XW1 = feat @ W_gc1 — fp16 split-3 (fp32-class accuracy; feeds degree cliff)
    {
        dim3 grid(HID / 128, cdiv(NNODES, 128));
        hmma_gemm_kernel<0, 0, false><<<grid, 256, H_SMEM_TOTAL>>>(
            fhi, whi_gc1, nullptr, bufA, nullptr, NNODES, HID, 512, 512);
        hmma_gemm_kernel<0, 0, true><<<grid, 256, H_SMEM_TOTAL>>>(
            fhi, wlo_gc1, nullptr, bufA, nullptr, NNODES, HID, 512, 512);
        hmma_gemm_kernel<0, 0, true><<<grid, 256, H_SMEM_TOTAL>>>(
            flo, whi_gc1, nullptr, bufA, nullptr, NNODES, HID, 512, 512);
    }
    // 2) h = relu(spmm + b1) — CSR gather
    spmm_gather_kernel<256, false><<<cdiv(NNODES, 8), TB>>>(off_enc, ecol, eval, bufA, b_gc1, bufB, NNODES);
    // 3) hW2 = h @ W_gc2 — fp32 SIMT (exact)
    {
        dim3 grid(cdiv(LAT, BN), cdiv(NNODES, BM));
        sgemm_kernel<<<grid, TB>>>(bufB, W_gc2, bufA, NNODES, LAT, HID);
    }
    // 4) z = relu(spmm + b2)
    spmm_gather_kernel<64, false><<<cdiv(NNODES, 8), TB>>>(off_enc, ecol, eval, bufA, b_gc2, z, NNODES);
    // 5) degree + pred_deg
    degree_kernel<<<cdiv(NNODES, TB / 32), TB>>>(z, W_reg, b_reg, out_deg, pdeg, NNODES);
    // 5b) mend CSR build
    cudaMemsetAsync(cnt, 0, NODE_LEN * sizeof(int));
    mend_hist_edges_kernel<<<cdiv(E, TB), TB>>>(edges, E);
    mend_hist_new_kernel<<<cdiv(NNODES * NPRED, TB), TB>>>(pdeg);
    scan_kernel<<<1, 1024>>>(cnt, off_mend, fill, NODE_LEN);
    mend_fill_edges_kernel<<<cdiv(E, TB), TB>>>(edges, E);
    mend_fill_new_kernel<<<cdiv(NNODES * NPRED, TB), TB>>>(pdeg);
    // 6) znh = half(z + noise)
    add_half_kernel<<<cdiv((long long)NNODES * LAT, TB), TB>>>(znh, z, noise, (long long)NNODES * LAT);
    // 7) g1h = half(relu(znh @ W_fc1 + b)) — fp16 mma
    {
        dim3 grid(FC1N / 128, cdiv(NNODES, 128));
        hmma_gemm_kernel<1, 1, false><<<grid, 256, H_SMEM_TOTAL>>>(
            znh, wh_fc1, b_fc1, nullptr, g1h, NNODES, FC1N, LAT, LAT);
    }
    // 8) g2h = half(relu(g1h @ W_fc2 + b)) — fp16 mma
    {
        dim3 grid(FC2N / 128, cdiv(NNODES, 128));
        hmma_gemm_kernel<1, 1, false><<<grid, 256, H_SMEM_TOTAL>>>(
            g1h, wh_fc2, b_fc2, nullptr, g2h, NNODES, FC2N, FC1N, 256);
    }
    // 9) gen_feat = tanh(g2h @ W_flat + b) — fp16 mma; f32 out_gen + half fillh gen rows
    {
        dim3 grid(2560 / 128, cdiv(NNODES, 128));
        hmma_gemm_kernel<2, 2, false><<<grid, 256, H_SMEM_TOTAL>>>(
            g2h, wh_flat, b_flat, out_gen, fillh, NNODES, GENF, FC2N, 2048);
    }
    // 10) fillW3 = fillh @ W_gc3 — fp16 mma (K padded to 512)
    {
        dim3 grid(HID / 128, cdiv(NODE_LEN, 128));
        hmma_gemm_kernel<0, 0, false><<<grid, 256, H_SMEM_TOTAL>>>(
            fillh, wh_gc3, nullptr, bufA, nullptr, NODE_LEN, HID, 512, 512);
    }
    // 12+13) mend layer 1 gather fused with gc4 skinny GEMM -> c7
    mend_gather_gc4_kernel<<<cdiv(NODE_LEN, 8), TB>>>(off_mend, mcol, bufA, b_gc3, W_gc4, c7, NODE_LEN);
    // 14) mend layer 2 — CSR gather
    spmm_gather_kernel<16, true><<<cdiv(NODE_LEN, 8), TB>>>(off_mend, mcol, nullptr, c7, b_gc4, out_nc, NODE_LEN);

    (void)n_in; (void)out_size;
}

// round 11
// speedup vs baseline: 1.2290x; 1.2290x over previous
#include <cuda_runtime.h>
#include <cuda_fp16.h>
#include <cstdint>

// ---------------- problem constants ----------------
#define NNODES   20000
#define FEAT     500
#define HID      256
#define LAT      64
#define NPRED    5
#define NCLS     16
#define NODE_LEN (NNODES + NNODES * NPRED)      // 120000
#define GENF     (NPRED * FEAT)                 // 2500
#define FC1N     256
#define FC2N     2048

#define OUT_GEN_OFF ((long long)NNODES)
#define OUT_NC_OFF  ((long long)NNODES + (long long)NNODES * GENF)

// ---------------- scratch (static device globals; no allocation) ------------
__device__ float g_bufA[(size_t)NODE_LEN * HID];
__device__ float g_bufB[(size_t)NODE_LEN * HID];
__device__ float g_z[(size_t)NNODES * LAT];
__device__ float g_c7[(size_t)NODE_LEN * NCLS];
__device__ int   g_pdeg[NNODES];
__device__ int   g_is64;
// fp16 operands
__device__ __half g_g1h[(size_t)NNODES * FC1N];
__device__ __half g_g2h[(size_t)NNODES * FC2N];
__device__ __half g_fillh[(size_t)NODE_LEN * 512];
__device__ __half g_znh[(size_t)NNODES * LAT];
__device__ __half g_wh_fc2[(size_t)2048 * 256];
__device__ __half g_wh_flat[(size_t)2560 * 2048];
__device__ __half g_wh_gc3[(size_t)256 * 512];
__device__ __half g_wh_fc1[(size_t)256 * 64];
// CSR scratch
__device__ int   g_cnt[NODE_LEN];
__device__ int   g_fill[NODE_LEN];
__device__ int   g_off_enc[NNODES + 1];
__device__ int   g_off_mend[NODE_LEN + 1];
__device__ int   g_ecol[700000];
__device__ float g_eval[700000];
__device__ int   g_mcol[900000];

// ---------------- helpers ----------------
__device__ __forceinline__ uint32_t smem_u32(const void* p) {
    uint32_t a;
    asm("{ .reg .u64 t; cvta.to.shared.u64 t, %1; cvt.u32.u64 %0, t; }" : "=r"(a) : "l"(p));
    return a;
}
__device__ __forceinline__ void ldsm_x4(uint32_t addr, uint32_t* r) {
    asm volatile("ldmatrix.sync.aligned.m8n8.x4.shared.b16 {%0,%1,%2,%3}, [%4];"
                 : "=r"(r[0]), "=r"(r[1]), "=r"(r[2]), "=r"(r[3]) : "r"(addr));
}
__device__ __forceinline__ void mma_f16(float* c, const uint32_t* a, uint32_t b0, uint32_t b1) {
    asm volatile(
        "mma.sync.aligned.m16n8k16.row.col.f32.f16.f16.f32 "
        "{%0,%1,%2,%3}, {%4,%5,%6,%7}, {%8,%9}, {%0,%1,%2,%3};"
        : "+f"(c[0]), "+f"(c[1]), "+f"(c[2]), "+f"(c[3])
        : "r"(a[0]), "r"(a[1]), "r"(a[2]), "r"(a[3]), "r"(b0), "r"(b1));
}
#define CP_ASYNC16(dst, src) \
    asm volatile("cp.async.cg.shared.global [%0], [%1], 16;" :: "r"(dst), "l"(src))
#define CP_COMMIT() asm volatile("cp.async.commit_group;" ::: "memory")
#define CP_WAIT(n)  asm volatile("cp.async.wait_group %0;" :: "n"(n) : "memory")

// ---------------- index dtype detection ----------------
__global__ void detect_idx_kernel(const void* adj_rows) {
    int lane = threadIdx.x;
    const long long* p = (const long long*)adj_rows;
    int bad = 0;
    for (int i = lane; i < 256; i += 32) {
        long long v = p[i];
        if (v < 0 || v >= NODE_LEN) bad = 1;
    }
    unsigned m = __ballot_sync(0xffffffffu, bad);
    if (lane == 0) g_is64 = (m == 0) ? 1 : 0;
}
__device__ __forceinline__ long long load_idx(const void* p, long long i) {
    return g_is64 ? ((const long long*)p)[i] : (long long)((const int*)p)[i];
}

// ---------------- CSR build ----------------
__global__ void enc_hist_kernel(const void* __restrict__ rows, long long nnz) {
    long long e = (long long)blockIdx.x * blockDim.x + threadIdx.x;
    if (e >= nnz) return;
    atomicAdd(&g_cnt[load_idx(rows, e)], 1);
}
__global__ void enc_fill_kernel(const void* __restrict__ rows, const void* __restrict__ cols,
                                const float* __restrict__ vals, long long nnz) {
    long long e = (long long)blockIdx.x * blockDim.x + threadIdx.x;
    if (e >= nnz) return;
    int r = (int)load_idx(rows, e);
    int pos = atomicAdd(&g_fill[r], 1);
    g_ecol[pos] = (int)load_idx(cols, e);
    g_eval[pos] = vals[e];
}
__global__ void scan_kernel(const int* __restrict__ cnt, int* __restrict__ off,
                            int* __restrict__ fill, int n) {
    __shared__ int part[1024];
    int t = threadIdx.x;
    int chunk = (n + 1023) >> 10;
    int lo = t * chunk, hi = lo + chunk;
    if (hi > n) hi = n;
    int s = 0;
    for (int i = lo; i < hi; i++) s += cnt[i];
    part[t] = s;
    __syncthreads();
    for (int d = 1; d < 1024; d <<= 1) {
        int add = (t >= d) ? part[t - d] : 0;
        __syncthreads();
        part[t] += add;
        __syncthreads();
    }
    int run = part[t] - s;
    for (int i = lo; i < hi; i++) {
        off[i] = run; fill[i] = run;
        run += cnt[i];
    }
    if (t == 1023) off[n] = part[1023];
}
__global__ void mend_hist_edges_kernel(const void* __restrict__ edges, int E) {
    int e = blockIdx.x * blockDim.x + threadIdx.x;
    if (e >= E) return;
    int lo = (int)load_idx(edges, 2LL * e);
    int hi = (int)load_idx(edges, 2LL * e + 1);
    atomicAdd(&g_cnt[lo], 1);
    atomicAdd(&g_cnt[hi], 1);
}
__global__ void mend_hist_new_kernel(const int* __restrict__ pdeg) {
    int t = blockIdx.x * blockDim.x + threadIdx.x;
    if (t >= NNODES * NPRED) return;
    int node = t / NPRED, j = t - node * NPRED;
    if (j < pdeg[node]) {
        atomicAdd(&g_cnt[node], 1);
        g_cnt[NNODES + t] = 1;
    }
}
__global__ void mend_fill_edges_kernel(const void* __restrict__ edges, int E) {
    int e = blockIdx.x * blockDim.x + threadIdx.x;
    if (e >= E) return;
    int lo = (int)load_idx(edges, 2LL * e);
    int hi = (int)load_idx(edges, 2LL * e + 1);
    int p0 = atomicAdd(&g_fill[lo], 1);
    g_mcol[p0] = hi;
    int p1 = atomicAdd(&g_fill[hi], 1);
    g_mcol[p1] = lo;
}
__global__ void mend_fill_new_kernel(const int* __restrict__ pdeg) {
    int t = blockIdx.x * blockDim.x + threadIdx.x;
    if (t >= NNODES * NPRED) return;
    int node = t / NPRED, j = t - node * NPRED;
    if (j < pdeg[node]) {
        int p0 = atomicAdd(&g_fill[node], 1);
        g_mcol[p0] = NNODES + t;
        g_mcol[g_off_mend[NNODES + t]] = node;
    }
}

// ---------------- gather SpMM (warp per row) ----------------
template <int D, bool MEND>
__global__ void spmm_gather_kernel(const int* __restrict__ off, const int* __restrict__ cols,
                                   const float* __restrict__ vals,
                                   const float* __restrict__ x, const float* __restrict__ bias,
                                   float* __restrict__ y, int nrows)
{
    int w = (int)(((long long)blockIdx.x * blockDim.x + threadIdx.x) >> 5);
    int lane = threadIdx.x & 31;
    if (w >= nrows) return;
    int e0 = off[w], e1 = off[w + 1];

    if (D == 256) {
        float a[8] = {0, 0, 0, 0, 0, 0, 0, 0};
        const int cb = lane * 4;
        for (int e = e0; e < e1; e++) {
            long long c = cols[e];
            float4 t0 = *(const float4*)(x + c * 256 + cb);
            float4 t1 = *(const float4*)(x + c * 256 + 128 + cb);
            if (MEND) {
                a[0] += t0.x; a[1] += t0.y; a[2] += t0.z; a[3] += t0.w;
                a[4] += t1.x; a[5] += t1.y; a[6] += t1.z; a[7] += t1.w;
            } else {
                float v = vals[e];
                a[0] += v * t0.x; a[1] += v * t0.y; a[2] += v * t0.z; a[3] += v * t0.w;
                a[4] += v * t1.x; a[5] += v * t1.y; a[6] += v * t1.z; a[7] += v * t1.w;
            }
        }
        float4 o0, o1;
        if (MEND) {
            float inv = 1.0f / (1.0f + (float)(e1 - e0));
            const float* xr = x + (long long)w * 256;
            o0.x = fmaxf((a[0] + xr[cb + 0]) * inv + bias[cb + 0], 0.f);
            o0.y = fmaxf((a[1] + xr[cb + 1]) * inv + bias[cb + 1], 0.f);
            o0.z = fmaxf((a[2] + xr[cb + 2]) * inv + bias[cb + 2], 0.f);
            o0.w = fmaxf((a[3] + xr[cb + 3]) * inv + bias[cb + 3], 0.f);
            o1.x = fmaxf((a[4] + xr[128 + cb + 0]) * inv + bias[128 + cb + 0], 0.f);
            o1.y = fmaxf((a[5] + xr[128 + cb + 1]) * inv + bias[128 + cb + 1], 0.f);
            o1.z = fmaxf((a[6] + xr[128 + cb + 2]) * inv + bias[128 + cb + 2], 0.f);
            o1.w = fmaxf((a[7] + xr[128 + cb + 3]) * inv + bias[128 + cb + 3], 0.f);
        } else {
            o0.x = fmaxf(a[0] + bias[cb + 0], 0.f);
            o0.y = fmaxf(a[1] + bias[cb + 1], 0.f);
            o0.z = fmaxf(a[2] + bias[cb + 2], 0.f);
            o0.w = fmaxf(a[3] + bias[cb + 3], 0.f);
            o1.x = fmaxf(a[4] + bias[128 + cb + 0], 0.f);
            o1.y = fmaxf(a[5] + bias[128 + cb + 1], 0.f);
            o1.z = fmaxf(a[6] + bias[128 + cb + 2], 0.f);
            o1.w = fmaxf(a[7] + bias[128 + cb + 3], 0.f);
        }
        *(float4*)(y + (long long)w * 256 + cb) = o0;
        *(float4*)(y + (long long)w * 256 + 128 + cb) = o1;
    } else if (D == 64) {
        float a0 = 0.f, a1 = 0.f;
        const int cb = lane * 2;
        for (int e = e0; e < e1; e++) {
            long long c = cols[e];
            float2 t = *(const float2*)(x + c * 64 + cb);
            if (MEND) { a0 += t.x; a1 += t.y; }
            else { float v = vals[e]; a0 += v * t.x; a1 += v * t.y; }
        }
        float2 o;
        if (MEND) {
            float inv = 1.0f / (1.0f + (float)(e1 - e0));
            const float* xr = x + (long long)w * 64;
            o.x = fmaxf((a0 + xr[cb + 0]) * inv + bias[cb + 0], 0.f);
            o.y = fmaxf((a1 + xr[cb + 1]) * inv + bias[cb + 1], 0.f);
        } else {
            o.x = fmaxf(a0 + bias[cb + 0], 0.f);
            o.y = fmaxf(a1 + bias[cb + 1], 0.f);
        }
        *(float2*)(y + (long long)w * 64 + cb) = o;
    } else {
        if (lane < 16) {
            float a = 0.f;
            for (int e = e0; e < e1; e++)
                a += x[(long long)cols[e] * 16 + lane];
            float inv = 1.0f / (1.0f + (float)(e1 - e0));
            float v = (a + x[(long long)w * 16 + lane]) * inv + bias[lane];
            y[(long long)w * 16 + lane] = fmaxf(v, 0.f);
        }
    }
}

// ---------------- weight transpose -> half: W[K,N] -> WT[Npad,Kpad] --------
__global__ void transpose_half_kernel(const float* __restrict__ W, __half* __restrict__ WT,
                                      int K, int N, int Kpad, int Npad) {
    __shared__ float tile[32][33];
    int kb = blockIdx.x * 32, nb = blockIdx.y * 32;
    int tx = threadIdx.x, ty = threadIdx.y;   // 32 x 8
#pragma unroll
    for (int i = 0; i < 4; i++) {
        int k = kb + ty + i * 8, n = nb + tx;
        tile[ty + i * 8][tx] = (k < K && n < N) ? W[(long long)k * N + n] : 0.0f;
    }
    __syncthreads();
#pragma unroll
    for (int i = 0; i < 4; i++) {
        int n = nb + ty + i * 8, k = kb + tx;
        if (n < Npad && k < Kpad)
            WT[(long long)n * Kpad + k] = __float2half_rn(tile[tx][ty + i * 8]);
    }
}

// feat -> fillh rows [0, NNODES), padded K=512
__global__ void feat_to_fillh_kernel(const float* __restrict__ feat, __half* __restrict__ fillh) {
    long long i = (long long)blockIdx.x * blockDim.x + threadIdx.x;
    if (i >= (long long)NNODES * 512) return;
    int r = (int)(i >> 9), c = (int)(i & 511);
    fillh[i] = (c < FEAT) ? __float2half_rn(feat[(long long)r * FEAT + c]) : __half(0.0f);
}
// znh = half(z + noise)
__global__ void add_half_kernel(__half* __restrict__ o, const float* __restrict__ a,
                                const float* __restrict__ b, long long n)
{
    long long i = (long long)blockIdx.x * blockDim.x + threadIdx.x;
    if (i < n) o[i] = __float2half_rn(a[i] + b[i]);
}

// ---------------- fp16 mma GEMM: C[M,N] = A[M,K] @ W[K,N] ------------------
// A: half [M,K] row-major; BT: half [Npad,Kpad] n-major.
// CTA tile 128x128, 8 warps (4m x 2n), warp tile 32x64, m16n8k16.
// Single __syncthreads per mainloop iteration (CUTLASS multistage ordering).
#define HSTAGES 4
#define H_STRIDE_B 80
#define H_MAT_BYTES (128 * H_STRIDE_B)          // 10240
#define H_STAGE_BYTES (2 * H_MAT_BYTES)         // 20480
#define H_SMEM_TOTAL (HSTAGES * H_STAGE_BYTES)  // 81920

// EPI: 0 none, 1 bias+relu, 2 bias+tanh.  OUT: 0 f32 C, 1 half Ch, 2 f32 C + genh->fillh
template <int EPI, int OUT>
__global__ void __launch_bounds__(256, 2) hmma_gemm_kernel(
    const __half* __restrict__ A, const __half* __restrict__ BT,
    const float* __restrict__ bias,
    float* __restrict__ C, __half* __restrict__ Ch,
    int M, int N, int K, int Kpad)
{
    extern __shared__ char smem[];
    const uint32_t sbase = smem_u32(smem);
    const int tid = threadIdx.x;
    const int wid = tid >> 5, lane = tid & 31;
    const int gid = lane >> 2, tig = lane & 3;
    const int warp_m = wid & 3, warp_n = wid >> 2;
    const int m0 = blockIdx.y * 128, n0 = blockIdx.x * 128;

    const int crow = tid >> 1;
    const int cboff = (tid & 1) * 32;

    const __half* aptr;
    {
        int r = m0 + crow;
        int rr = (r < M) ? r : (M - 1);
        aptr = A + (long long)rr * K;
    }
    const __half* bptr = BT + (long long)(n0 + crow) * Kpad;

    const uint32_t sA_wr = sbase + (uint32_t)crow * H_STRIDE_B + (uint32_t)cboff;
    const uint32_t sB_wr = sA_wr + H_MAT_BYTES;

    const int nChunks = K >> 5;

    auto issue = [&](int chunk) {
        int s = chunk & (HSTAGES - 1);
        uint32_t da = sA_wr + (uint32_t)s * H_STAGE_BYTES;
        uint32_t db = sB_wr + (uint32_t)s * H_STAGE_BYTES;
        const char* ga = (const char*)aptr + chunk * 64 + cboff;
        const char* gb = (const char*)bptr + chunk * 64 + cboff;
        CP_ASYNC16(da, ga); CP_ASYNC16(da + 16, ga + 16);
        CP_ASYNC16(db, gb); CP_ASYNC16(db + 16, gb + 16);
        CP_COMMIT();
    };

    float acc[2][8][4];
#pragma unroll
    for (int f = 0; f < 2; f++)
#pragma unroll
        for (int j = 0; j < 8; j++)
#pragma unroll
            for (int q = 0; q < 4; q++) acc[f][j][q] = 0.0f;

    // prologue: exactly HSTAGES-1 groups committed (real or empty)
    int pro = (HSTAGES - 1 < nChunks) ? HSTAGES - 1 : nChunks;
    for (int s = 0; s < pro; s++) issue(s);
    for (int s = pro; s < HSTAGES - 1; s++) CP_COMMIT();

    uint32_t a_off[2];
#pragma unroll
    for (int f = 0; f < 2; f++) {
        uint32_t row = (uint32_t)(warp_m * 32 + f * 16 + (lane & 15));
        uint32_t colb = (uint32_t)((lane >> 4) << 4);
        a_off[f] = row * H_STRIDE_B + colb;
    }
    uint32_t b_off[4];
#pragma unroll
    for (int jp = 0; jp < 4; jp++) {
        uint32_t row = (uint32_t)(warp_n * 64 + jp * 16 + ((lane >> 4) << 3) + (lane & 7));
        uint32_t colb = (uint32_t)(((lane >> 3) & 1) << 4);
        b_off[jp] = row * H_STRIDE_B + colb;
    }

    // ensure stage 0 ready before first compute
    CP_WAIT(HSTAGES - 2);
    __syncthreads();

    for (int i = 0; i < nChunks; i++) {
        // compute stage i
        uint32_t sA = sbase + (uint32_t)(i & (HSTAGES - 1)) * H_STAGE_BYTES;
        uint32_t sB = sA + H_MAT_BYTES;
#pragma unroll
        for (int kk = 0; kk < 2; kk++) {
            uint32_t afr[2][4];
            ldsm_x4(sA + a_off[0] + kk * 32, afr[0]);
            ldsm_x4(sA + a_off[1] + kk * 32, afr[1]);
#pragma unroll
            for (int jp = 0; jp < 4; jp++) {
                uint32_t br[4];
                ldsm_x4(sB + b_off[jp] + kk * 32, br);
                mma_f16(acc[0][2 * jp + 0], afr[0], br[0], br[1]);
                mma_f16(acc[1][2 * jp + 0], afr[1], br[0], br[1]);
                mma_f16(acc[0][2 * jp + 1], afr[0], br[2], br[3]);
                mma_f16(acc[1][2 * jp + 1], afr[1], br[2], br[3]);
            }
        }
        // issue stage i+HSTAGES-1 (WAR vs compute(i-1) protected by prior barrier)
        if (i + HSTAGES - 1 < nChunks) issue(i + HSTAGES - 1);
        else CP_COMMIT();
        CP_WAIT(HSTAGES - 2);      // stage i+1 ready
        __syncthreads();           // publish + separate from next issue
    }

#pragma unroll
    for (int f = 0; f < 2; f++) {
#pragma unroll
        for (int rr = 0; rr < 2; rr++) {
            int r = m0 + warp_m * 32 + f * 16 + rr * 8 + gid;
            if (r >= M) continue;
#pragma unroll
            for (int j = 0; j < 8; j++) {
                int c = n0 + warp_n * 64 + j * 8 + tig * 2;
                if (c >= N) continue;
                float v0 = acc[f][j][rr * 2 + 0], v1 = acc[f][j][rr * 2 + 1];
                if (EPI >= 1) { v0 += bias[c]; v1 += bias[c + 1]; }
                if (EPI == 1) { v0 = fmaxf(v0, 0.f); v1 = fmaxf(v1, 0.f); }
                if (EPI == 2) { v0 = tanhf(v0); v1 = tanhf(v1); }
                if (OUT == 0) {
                    *(float2*)(C + (long long)r * N + c) = make_float2(v0, v1);
                } else if (OUT == 1) {
                    *(__half2*)(Ch + (long long)r * N + c) = __floats2half2_rn(v0, v1);
                } else {
                    *(float2*)(C + (long long)r * N + c) = make_float2(v0, v1);
                    int j5 = c / FEAT, cc = c - j5 * FEAT;
                    *(__half2*)(Ch + ((size_t)(NNODES + r * NPRED + j5) * 512 + cc)) =
                        __floats2half2_rn(v0, v1);
                }
            }
        }
    }
}

// ---------------- SIMT SGEMM (precision-critical GEMMs: steps 1, 3) ----
#define BM 128
#define BN 128
#define BK 8
template <int EPI, bool OUTH>
__global__ void __launch_bounds__(256, 2) sgemm_kernel(
    const float* __restrict__ A, const float* __restrict__ B,
    const float* __restrict__ bias, float* __restrict__ C, __half* __restrict__ Ch,
    int M, int N, int K)
{
    __shared__ float As[BK][BM];
    __shared__ float Bs[BK][BN];
    const int tid = threadIdx.x;
    const int tx = tid & 15, ty = tid >> 4;
    const int rbase = blockIdx.y * BM, cbase = blockIdx.x * BN;
    float acc[8][8];
#pragma unroll
    for (int i = 0; i < 8; i++)
#pragma unroll
        for (int j = 0; j < 8; j++) acc[i][j] = 0.0f;
    const int arow = tid >> 1, acol = (tid & 1) * 4;
    const int brow = tid >> 5, bcol = (tid & 31) * 4;
    const float* arowptr = (rbase + arow < M) ? A + (long long)(rbase + arow) * K : nullptr;

    for (int kt = 0; kt < K; kt += BK) {
        float4 av = make_float4(0.f, 0.f, 0.f, 0.f);
        if (arowptr) {
            int kc = kt + acol;
            if (kc + 3 < K) av = *(const float4*)(arowptr + kc);
            else {
                if (kc + 0 < K) av.x = arowptr[kc + 0];
                if (kc + 1 < K) av.y = arowptr[kc + 1];
                if (kc + 2 < K) av.z = arowptr[kc + 2];
                if (kc + 3 < K) av.w = arowptr[kc + 3];
            }
        }
        As[acol + 0][arow] = av.x; As[acol + 1][arow] = av.y;
        As[acol + 2][arow] = av.z; As[acol + 3][arow] = av.w;
        float4 bv = make_float4(0.f, 0.f, 0.f, 0.f);
        {
            int kr = kt + brow, cc = cbase + bcol;
            if (kr < K) {
                const float* bp = B + (long long)kr * N + cc;
                if (cc + 3 < N) bv = *(const float4*)bp;
                else {
                    if (cc + 0 < N) bv.x = bp[0];
                    if (cc + 1 < N) bv.y = bp[1];
                    if (cc + 2 < N) bv.z = bp[2];
                    if (cc + 3 < N) bv.w = bp[3];
                }
            }
        }
        *(float4*)&Bs[brow][bcol] = bv;
        __syncthreads();
#pragma unroll
        for (int k = 0; k < BK; k++) {
            float ra[8], rb[8];
            *(float4*)&ra[0] = *(const float4*)&As[k][ty * 4];
            *(float4*)&ra[4] = *(const float4*)&As[k][64 + ty * 4];
            *(float4*)&rb[0] = *(const float4*)&Bs[k][tx * 4];
            *(float4*)&rb[4] = *(const float4*)&Bs[k][64 + tx * 4];
#pragma unroll
            for (int i = 0; i < 8; i++)
#pragma unroll
                for (int j = 0; j < 8; j++) acc[i][j] += ra[i] * rb[j];
        }
        __syncthreads();
    }
#pragma unroll
    for (int i = 0; i < 8; i++) {
        int r = rbase + ((i < 4) ? (ty * 4 + i) : (64 + ty * 4 + i - 4));
        if (r >= M) continue;
#pragma unroll
        for (int j = 0; j < 8; j++) {
            int c = cbase + ((j < 4) ? (tx * 4 + j) : (64 + tx * 4 + j - 4));
            if (c >= N) continue;
            float v = acc[i][j];
            if (EPI >= 1) v += bias[c];
            if (EPI == 1) v = fmaxf(v, 0.0f);
            if (OUTH) Ch[(long long)r * N + c] = __float2half_rn(v);
            else      C[(long long)r * N + c] = v;
        }
    }
}

// ---------------- skinny GEMM for gc4 ----------------
__global__ void skinny16_kernel(const float* __restrict__ X, const float* __restrict__ W,
                                float* __restrict__ C, int M)
{
    __shared__ float Ws[256 * 16];
    int tid = threadIdx.x;   // 128
    for (int i = tid; i < 256 * 16; i += 128) Ws[i] = W[i];
    __syncthreads();
    int r = blockIdx.x * 128 + tid;
    if (r >= M) return;
    const float* x = X + (long long)r * 256;
    float acc[16];
#pragma unroll
    for (int q = 0; q < 16; q++) acc[q] = 0.0f;
    for (int k = 0; k < 256; k += 4) {
        float4 a = *(const float4*)(x + k);
#pragma unroll
        for (int q = 0; q < 16; q++)
            acc[q] += a.x * Ws[(k + 0) * 16 + q] + a.y * Ws[(k + 1) * 16 + q]
                    + a.z * Ws[(k + 2) * 16 + q] + a.w * Ws[(k + 3) * 16 + q];
    }
    float* co = C + (long long)r * 16;
#pragma unroll
    for (int q = 0; q < 16; q += 4)
        *(float4*)(co + q) = make_float4(acc[q], acc[q + 1], acc[q + 2], acc[q + 3]);
}

// ---------------- misc ----------------
__global__ void degree_kernel(const float* __restrict__ z, const float* __restrict__ Wr,
                              const float* __restrict__ br, float* __restrict__ deg_out,
                              int* __restrict__ pdeg, int n)
{
    int r = blockIdx.x * (blockDim.x >> 5) + (threadIdx.x >> 5);
    int lane = threadIdx.x & 31;
    if (r >= n) return;
    float s = z[(long long)r * LAT + lane] * Wr[lane]
            + z[(long long)r * LAT + 32 + lane] * Wr[32 + lane];
#pragma unroll
    for (int o = 16; o; o >>= 1) s += __shfl_xor_sync(0xffffffffu, s, o);
    if (lane == 0) {
        float d = fmaxf(s + br[0], 0.0f);
        deg_out[r] = d;
        int pi = (int)d;
        if (pi > NPRED) pi = NPRED;
        pdeg[r] = pi;
    }
}

// ---------------- host ----------------
static inline int cdiv(long long a, long long b) { return (int)((a + b - 1) / b); }

extern "C" void kernel_launch(void* const* d_in, const int* in_sizes, int n_in,
                              void* d_out, int out_size)
{
    const float* feat     = (const float*)d_in[0];
    const void*  edges    = d_in[1];
    const void*  adj_rows = d_in[2];
    const void*  adj_cols = d_in[3];
    const float* adj_vals = (const float*)d_in[4];
    const float* noise    = (const float*)d_in[5];
    const float* W_gc1 = (const float*)d_in[6];   const float* b_gc1 = (const float*)d_in[7];
    const float* W_gc2 = (const float*)d_in[8];   const float* b_gc2 = (const float*)d_in[9];
    const float* W_reg = (const float*)d_in[10];  const float* b_reg = (const float*)d_in[11];
    const float* W_fc1 = (const float*)d_in[12];  const float* b_fc1 = (const float*)d_in[13];
    const float* W_fc2 = (const float*)d_in[14];  const float* b_fc2 = (const float*)d_in[15];
    const float* W_flat = (const float*)d_in[16]; const float* b_flat = (const float*)d_in[17];
    const float* W_gc3 = (const float*)d_in[18];  const float* b_gc3 = (const float*)d_in[19];
    const float* W_gc4 = (const float*)d_in[20];  const float* b_gc4 = (const float*)d_in[21];

    float* out = (float*)d_out;
    float* out_deg = out;
    float* out_gen = out + OUT_GEN_OFF;
    float* out_nc  = out + OUT_NC_OFF;

    const long long nnz_adj = in_sizes[2];
    const int E = in_sizes[1] / 2;

    void* p;
    float *bufA, *bufB, *z, *c7;
    __half *g1h, *g2h, *fillh, *znh, *wh_fc2, *wh_flat, *wh_gc3, *wh_fc1;
    int *pdeg, *cnt, *fill, *off_enc, *off_mend, *ecol, *mcol;
    float *eval;
    cudaGetSymbolAddress(&p, g_bufA);  bufA  = (float*)p;
    cudaGetSymbolAddress(&p, g_bufB);  bufB  = (float*)p;
    cudaGetSymbolAddress(&p, g_z);     z     = (float*)p;
    cudaGetSymbolAddress(&p, g_c7);    c7    = (float*)p;
    cudaGetSymbolAddress(&p, g_pdeg);  pdeg  = (int*)p;
    cudaGetSymbolAddress(&p, g_cnt);   cnt   = (int*)p;
    cudaGetSymbolAddress(&p, g_fill);  fill  = (int*)p;
    cudaGetSymbolAddress(&p, g_off_enc);  off_enc  = (int*)p;
    cudaGetSymbolAddress(&p, g_off_mend); off_mend = (int*)p;
    cudaGetSymbolAddress(&p, g_ecol);  ecol  = (int*)p;
    cudaGetSymbolAddress(&p, g_eval);  eval  = (float*)p;
    cudaGetSymbolAddress(&p, g_mcol);  mcol  = (int*)p;
    cudaGetSymbolAddress(&p, g_g1h);   g1h   = (__half*)p;
    cudaGetSymbolAddress(&p, g_g2h);   g2h   = (__half*)p;
    cudaGetSymbolAddress(&p, g_fillh); fillh = (__half*)p;
    cudaGetSymbolAddress(&p, g_znh);   znh   = (__half*)p;
    cudaGetSymbolAddress(&p, g_wh_fc2);  wh_fc2  = (__half*)p;
    cudaGetSymbolAddress(&p, g_wh_flat); wh_flat = (__half*)p;
    cudaGetSymbolAddress(&p, g_wh_gc3);  wh_gc3  = (__half*)p;
    cudaGetSymbolAddress(&p, g_wh_fc1);  wh_fc1  = (__half*)p;

    cudaFuncSetAttribute((const void*)hmma_gemm_kernel<1, 1>,
                         cudaFuncAttributeMaxDynamicSharedMemorySize, H_SMEM_TOTAL);
    cudaFuncSetAttribute((const void*)hmma_gemm_kernel<2, 2>,
                         cudaFuncAttributeMaxDynamicSharedMemorySize, H_SMEM_TOTAL);
    cudaFuncSetAttribute((const void*)hmma_gemm_kernel<0, 0>,
                         cudaFuncAttributeMaxDynamicSharedMemorySize, H_SMEM_TOTAL);

    const int TB = 256;
    dim3 tblk(32, 8);

    // 0) prep
    detect_idx_kernel<<<1, 32>>>(adj_rows);
    transpose_half_kernel<<<dim3(cdiv(256, 32), cdiv(2048, 32)), tblk>>>(W_fc2, wh_fc2, 256, 2048, 256, 2048);
    transpose_half_kernel<<<dim3(cdiv(2048, 32), cdiv(2560, 32)), tblk>>>(W_flat, wh_flat, 2048, 2500, 2048, 2560);
    transpose_half_kernel<<<dim3(cdiv(512, 32), cdiv(256, 32)), tblk>>>(W_gc3, wh_gc3, 500, 256, 512, 256);
    transpose_half_kernel<<<dim3(cdiv(64, 32), cdiv(256, 32)), tblk>>>(W_fc1, wh_fc1, 64, 256, 64, 256);
    feat_to_fillh_kernel<<<cdiv((long long)NNODES * 512, TB), TB>>>(feat, fillh);

    // 0b) encoder CSR build
    cudaMemsetAsync(cnt, 0, NNODES * sizeof(int));
    enc_hist_kernel<<<cdiv(nnz_adj, TB), TB>>>(adj_rows, nnz_adj);
    scan_kernel<<<1, 1024>>>(cnt, off_enc, fill, NNODES);
    enc_fill_kernel<<<cdiv(nnz_adj, TB), TB>>>(adj_rows, adj_cols, adj_vals, nnz_adj);

    // 1) XW1 = feat @ W_gc1 — fp32 exact (feeds int(degree) cliff)
    {
        dim3 grid(cdiv(HID, BN), cdiv(NNODES, BM));
        sgemm_kernel<0, false><<<grid, TB>>>(feat, W_gc1, nullptr, bufA, nullptr, NNODES, HID, FEAT);
    }
    // 2) h = relu(spmm + b1) — CSR gather
    spmm_gather_kernel<256, false><<<cdiv(NNODES, 8), TB>>>(off_enc, ecol, eval, bufA, b_gc1, bufB, NNODES);
    // 3) hW2 = h @ W_gc2 — fp32 exact
    {
        dim3 grid(cdiv(LAT, BN), cdiv(NNODES, BM));
        sgemm_kernel<0, false><<<grid, TB>>>(bufB, W_gc2, nullptr, bufA, nullptr, NNODES, LAT, HID);
    }
    // 4) z = relu(spmm + b2)
    spmm_gather_kernel<64, false><<<cdiv(NNODES, 8), TB>>>(off_enc, ecol, eval, bufA, b_gc2, z, NNODES);
    // 5) degree + pred_deg
    degree_kernel<<<cdiv(NNODES, TB / 32), TB>>>(z, W_reg, b_reg, out_deg, pdeg, NNODES);
    // 5b) mend CSR build
    cudaMemsetAsync(cnt, 0, NODE_LEN * sizeof(int));
    mend_hist_edges_kernel<<<cdiv(E, TB), TB>>>(edges, E);
    mend_hist_new_kernel<<<cdiv(NNODES * NPRED, TB), TB>>>(pdeg);
    scan_kernel<<<1, 1024>>>(cnt, off_mend, fill, NODE_LEN);
    mend_fill_edges_kernel<<<cdiv(E, TB), TB>>>(edges, E);
    mend_fill_new_kernel<<<cdiv(NNODES * NPRED, TB), TB>>>(pdeg);
    // 6) znh = half(z + noise)
    add_half_kernel<<<cdiv((long long)NNODES * LAT, TB), TB>>>(znh, z, noise, (long long)NNODES * LAT);
    // 7) g1h = half(relu(znh @ W_fc1 + b)) — fp16 mma (K=64)
    {
        dim3 grid(FC1N / 128, cdiv(NNODES, 128));
        hmma_gemm_kernel<1, 1><<<grid, 256, H_SMEM_TOTAL>>>(
            znh, wh_fc1, b_fc1, nullptr, g1h, NNODES, FC1N, LAT, LAT);
    }
    // 8) g2h = half(relu(g1h @ W_fc2 + b)) — fp16 mma
    {
        dim3 grid(FC2N / 128, cdiv(NNODES, 128));
        hmma_gemm_kernel<1, 1><<<grid, 256, H_SMEM_TOTAL>>>(
            g1h, wh_fc2, b_fc2, nullptr, g2h, NNODES, FC2N, FC1N, 256);
    }
    // 9) gen_feat = tanh(g2h @ W_flat + b) — fp16 mma; f32 out_gen + half fillh gen rows
    {
        dim3 grid(2560 / 128, cdiv(NNODES, 128));
        hmma_gemm_kernel<2, 2><<<grid, 256, H_SMEM_TOTAL>>>(
            g2h, wh_flat, b_flat, out_gen, fillh, NNODES, GENF, FC2N, 2048);
    }
    // 10) fillW3 = fillh @ W_gc3 — fp16 mma (K padded to 512)
    {
        dim3 grid(HID / 128, cdiv(NODE_LEN, 128));
        hmma_gemm_kernel<0, 0><<<grid, 256, H_SMEM_TOTAL>>>(
            fillh, wh_gc3, nullptr, bufA, nullptr, NODE_LEN, HID, 512, 512);
    }
    // 12) mend layer 1 — CSR gather, fused normalize+bias+relu
    spmm_gather_kernel<256, true><<<cdiv(NODE_LEN, 8), TB>>>(off_mend, mcol, nullptr, bufA, b_gc3, bufB, NODE_LEN);
    // 13) c7 = h2 @ W_gc4 — skinny N=16
    skinny16_kernel<<<cdiv(NODE_LEN, 128), 128>>>(bufB, W_gc4, c7, NODE_LEN);
    // 14) mend layer 2 — CSR gather
    spmm_gather_kernel<16, true><<<cdiv(NODE_LEN, 8), TB>>>(off_mend, mcol, nullptr, c7, b_gc4, out_nc, NODE_LEN);

    (void)n_in; (void)out_size;
}

// round 12
// speedup vs baseline: 1.2982x; 1.0563x over previous
#include <cuda_runtime.h>
#include <cuda_fp16.h>
#include <cstdint>

// ---------------- problem constants ----------------
#define NNODES   20000
#define FEAT     500
#define HID      256
#define LAT      64
#define NPRED    5
#define NCLS     16
#define NODE_LEN (NNODES + NNODES * NPRED)      // 120000
#define GENF     (NPRED * FEAT)                 // 2500
#define FC1N     256
#define FC2N     2048

#define OUT_GEN_OFF ((long long)NNODES)
#define OUT_NC_OFF  ((long long)NNODES + (long long)NNODES * GENF)

// ---------------- scratch (static device globals; no allocation) ------------
__device__ float g_bufA[(size_t)NODE_LEN * HID];
__device__ float g_bufB[(size_t)NODE_LEN * HID];
__device__ float g_z[(size_t)NNODES * LAT];
__device__ float g_c7[(size_t)NODE_LEN * NCLS];
__device__ int   g_pdeg[NNODES];
__device__ int   g_is64;
// fp16 operands
__device__ __half g_g1h[(size_t)NNODES * FC1N];
__device__ __half g_g2h[(size_t)NNODES * FC2N];
__device__ __half g_fillh[(size_t)NODE_LEN * 512];
__device__ __half g_fhi[(size_t)NNODES * 512];
__device__ __half g_flo[(size_t)NNODES * 512];
__device__ __half g_znh[(size_t)NNODES * 128];
__device__ __half g_wh_fc2[(size_t)2048 * 256];
__device__ __half g_wh_flat[(size_t)2560 * 2048];
__device__ __half g_wh_gc3[(size_t)256 * 512];
__device__ __half g_wh_fc1[(size_t)256 * 128];
__device__ __half g_whi_gc1[(size_t)256 * 512];
__device__ __half g_wlo_gc1[(size_t)256 * 512];
// CSR scratch
__device__ int   g_cnt[NODE_LEN];
__device__ int   g_fill[NODE_LEN];
__device__ int   g_off_enc[NNODES + 1];
__device__ int   g_off_mend[NODE_LEN + 1];
__device__ int   g_ecol[700000];
__device__ float g_eval[700000];
__device__ int   g_mcol[900000];

// ---------------- helpers ----------------
__device__ __forceinline__ uint32_t smem_u32(const void* p) {
    uint32_t a;
    asm("{ .reg .u64 t; cvta.to.shared.u64 t, %1; cvt.u32.u64 %0, t; }" : "=r"(a) : "l"(p));
    return a;
}
__device__ __forceinline__ void ldsm_x4(uint32_t addr, uint32_t* r) {
    asm volatile("ldmatrix.sync.aligned.m8n8.x4.shared.b16 {%0,%1,%2,%3}, [%4];"
                 : "=r"(r[0]), "=r"(r[1]), "=r"(r[2]), "=r"(r[3]) : "r"(addr));
}
__device__ __forceinline__ void mma_f16(float* c, const uint32_t* a, uint32_t b0, uint32_t b1) {
    asm volatile(
        "mma.sync.aligned.m16n8k16.row.col.f32.f16.f16.f32 "
        "{%0,%1,%2,%3}, {%4,%5,%6,%7}, {%8,%9}, {%0,%1,%2,%3};"
        : "+f"(c[0]), "+f"(c[1]), "+f"(c[2]), "+f"(c[3])
        : "r"(a[0]), "r"(a[1]), "r"(a[2]), "r"(a[3]), "r"(b0), "r"(b1));
}
#define CP_ASYNC16(dst, src) \
    asm volatile("cp.async.cg.shared.global [%0], [%1], 16;" :: "r"(dst), "l"(src))
#define CP_COMMIT() asm volatile("cp.async.commit_group;" ::: "memory")
#define CP_WAIT(n)  asm volatile("cp.async.wait_group %0;" :: "n"(n) : "memory")

// ---------------- index dtype detection ----------------
__global__ void detect_idx_kernel(const void* adj_rows) {
    int lane = threadIdx.x;
    const long long* p = (const long long*)adj_rows;
    int bad = 0;
    for (int i = lane; i < 256; i += 32) {
        long long v = p[i];
        if (v < 0 || v >= NODE_LEN) bad = 1;
    }
    unsigned m = __ballot_sync(0xffffffffu, bad);
    if (lane == 0) g_is64 = (m == 0) ? 1 : 0;
}
__device__ __forceinline__ long long load_idx(const void* p, long long i) {
    return g_is64 ? ((const long long*)p)[i] : (long long)((const int*)p)[i];
}

// ---------------- CSR build ----------------
__global__ void enc_hist_kernel(const void* __restrict__ rows, long long nnz) {
    long long e = (long long)blockIdx.x * blockDim.x + threadIdx.x;
    if (e >= nnz) return;
    atomicAdd(&g_cnt[load_idx(rows, e)], 1);
}
__global__ void enc_fill_kernel(const void* __restrict__ rows, const void* __restrict__ cols,
                                const float* __restrict__ vals, long long nnz) {
    long long e = (long long)blockIdx.x * blockDim.x + threadIdx.x;
    if (e >= nnz) return;
    int r = (int)load_idx(rows, e);
    int pos = atomicAdd(&g_fill[r], 1);
    g_ecol[pos] = (int)load_idx(cols, e);
    g_eval[pos] = vals[e];
}
__global__ void scan_kernel(const int* __restrict__ cnt, int* __restrict__ off,
                            int* __restrict__ fill, int n) {
    __shared__ int part[1024];
    int t = threadIdx.x;
    int chunk = (n + 1023) >> 10;
    int lo = t * chunk, hi = lo + chunk;
    if (hi > n) hi = n;
    int s = 0;
    for (int i = lo; i < hi; i++) s += cnt[i];
    part[t] = s;
    __syncthreads();
    for (int d = 1; d < 1024; d <<= 1) {
        int add = (t >= d) ? part[t - d] : 0;
        __syncthreads();
        part[t] += add;
        __syncthreads();
    }
    int run = part[t] - s;
    for (int i = lo; i < hi; i++) {
        off[i] = run; fill[i] = run;
        run += cnt[i];
    }
    if (t == 1023) off[n] = part[1023];
}
__global__ void mend_hist_edges_kernel(const void* __restrict__ edges, int E) {
    int e = blockIdx.x * blockDim.x + threadIdx.x;
    if (e >= E) return;
    int lo = (int)load_idx(edges, 2LL * e);
    int hi = (int)load_idx(edges, 2LL * e + 1);
    atomicAdd(&g_cnt[lo], 1);
    atomicAdd(&g_cnt[hi], 1);
}
__global__ void mend_hist_new_kernel(const int* __restrict__ pdeg) {
    int t = blockIdx.x * blockDim.x + threadIdx.x;
    if (t >= NNODES * NPRED) return;
    int node = t / NPRED, j = t - node * NPRED;
    if (j < pdeg[node]) {
        atomicAdd(&g_cnt[node], 1);
        g_cnt[NNODES + t] = 1;
    }
}
__global__ void mend_fill_edges_kernel(const void* __restrict__ edges, int E) {
    int e = blockIdx.x * blockDim.x + threadIdx.x;
    if (e >= E) return;
    int lo = (int)load_idx(edges, 2LL * e);
    int hi = (int)load_idx(edges, 2LL * e + 1);
    int p0 = atomicAdd(&g_fill[lo], 1);
    g_mcol[p0] = hi;
    int p1 = atomicAdd(&g_fill[hi], 1);
    g_mcol[p1] = lo;
}
__global__ void mend_fill_new_kernel(const int* __restrict__ pdeg) {
    int t = blockIdx.x * blockDim.x + threadIdx.x;
    if (t >= NNODES * NPRED) return;
    int node = t / NPRED, j = t - node * NPRED;
    if (j < pdeg[node]) {
        int p0 = atomicAdd(&g_fill[node], 1);
        g_mcol[p0] = NNODES + t;
        g_mcol[g_off_mend[NNODES + t]] = node;
    }
}

// ---------------- gather SpMM (warp per row) ----------------
template <int D, bool MEND>
__global__ void spmm_gather_kernel(const int* __restrict__ off, const int* __restrict__ cols,
                                   const float* __restrict__ vals,
                                   const float* __restrict__ x, const float* __restrict__ bias,
                                   float* __restrict__ y, int nrows)
{
    int w = (int)(((long long)blockIdx.x * blockDim.x + threadIdx.x) >> 5);
    int lane = threadIdx.x & 31;
    if (w >= nrows) return;
    int e0 = off[w], e1 = off[w + 1];

    if (D == 256) {
        float a[8] = {0, 0, 0, 0, 0, 0, 0, 0};
        const int cb = lane * 4;
        for (int e = e0; e < e1; e++) {
            long long c = cols[e];
            float4 t0 = *(const float4*)(x + c * 256 + cb);
            float4 t1 = *(const float4*)(x + c * 256 + 128 + cb);
            if (MEND) {
                a[0] += t0.x; a[1] += t0.y; a[2] += t0.z; a[3] += t0.w;
                a[4] += t1.x; a[5] += t1.y; a[6] += t1.z; a[7] += t1.w;
            } else {
                float v = vals[e];
                a[0] += v * t0.x; a[1] += v * t0.y; a[2] += v * t0.z; a[3] += v * t0.w;
                a[4] += v * t1.x; a[5] += v * t1.y; a[6] += v * t1.z; a[7] += v * t1.w;
            }
        }
        float4 o0, o1;
        if (MEND) {
            float inv = 1.0f / (1.0f + (float)(e1 - e0));
            const float* xr = x + (long long)w * 256;
            o0.x = fmaxf((a[0] + xr[cb + 0]) * inv + bias[cb + 0], 0.f);
            o0.y = fmaxf((a[1] + xr[cb + 1]) * inv + bias[cb + 1], 0.f);
            o0.z = fmaxf((a[2] + xr[cb + 2]) * inv + bias[cb + 2], 0.f);
            o0.w = fmaxf((a[3] + xr[cb + 3]) * inv + bias[cb + 3], 0.f);
            o1.x = fmaxf((a[4] + xr[128 + cb + 0]) * inv + bias[128 + cb + 0], 0.f);
            o1.y = fmaxf((a[5] + xr[128 + cb + 1]) * inv + bias[128 + cb + 1], 0.f);
            o1.z = fmaxf((a[6] + xr[128 + cb + 2]) * inv + bias[128 + cb + 2], 0.f);
            o1.w = fmaxf((a[7] + xr[128 + cb + 3]) * inv + bias[128 + cb + 3], 0.f);
        } else {
            o0.x = fmaxf(a[0] + bias[cb + 0], 0.f);
            o0.y = fmaxf(a[1] + bias[cb + 1], 0.f);
            o0.z = fmaxf(a[2] + bias[cb + 2], 0.f);
            o0.w = fmaxf(a[3] + bias[cb + 3], 0.f);
            o1.x = fmaxf(a[4] + bias[128 + cb + 0], 0.f);
            o1.y = fmaxf(a[5] + bias[128 + cb + 1], 0.f);
            o1.z = fmaxf(a[6] + bias[128 + cb + 2], 0.f);
            o1.w = fmaxf(a[7] + bias[128 + cb + 3], 0.f);
        }
        *(float4*)(y + (long long)w * 256 + cb) = o0;
        *(float4*)(y + (long long)w * 256 + 128 + cb) = o1;
    } else if (D == 64) {
        float a0 = 0.f, a1 = 0.f;
        const int cb = lane * 2;
        for (int e = e0; e < e1; e++) {
            long long c = cols[e];
            float2 t = *(const float2*)(x + c * 64 + cb);
            if (MEND) { a0 += t.x; a1 += t.y; }
            else { float v = vals[e]; a0 += v * t.x; a1 += v * t.y; }
        }
        float2 o;
        if (MEND) {
            float inv = 1.0f / (1.0f + (float)(e1 - e0));
            const float* xr = x + (long long)w * 64;
            o.x = fmaxf((a0 + xr[cb + 0]) * inv + bias[cb + 0], 0.f);
            o.y = fmaxf((a1 + xr[cb + 1]) * inv + bias[cb + 1], 0.f);
        } else {
            o.x = fmaxf(a0 + bias[cb + 0], 0.f);
            o.y = fmaxf(a1 + bias[cb + 1], 0.f);
        }
        *(float2*)(y + (long long)w * 64 + cb) = o;
    } else {
        if (lane < 16) {
            float a = 0.f;
            for (int e = e0; e < e1; e++)
                a += x[(long long)cols[e] * 16 + lane];
            float inv = 1.0f / (1.0f + (float)(e1 - e0));
            float v = (a + x[(long long)w * 16 + lane]) * inv + bias[lane];
            y[(long long)w * 16 + lane] = fmaxf(v, 0.f);
        }
    }
}

// ---------------- weight transpose -> half: W[K,N] -> WT[Npad,Kpad] --------
__global__ void transpose_half_kernel(const float* __restrict__ W, __half* __restrict__ WT,
                                      int K, int N, int Kpad, int Npad) {
    __shared__ float tile[32][33];
    int kb = blockIdx.x * 32, nb = blockIdx.y * 32;
    int tx = threadIdx.x, ty = threadIdx.y;   // 32 x 8
#pragma unroll
    for (int i = 0; i < 4; i++) {
        int k = kb + ty + i * 8, n = nb + tx;
        tile[ty + i * 8][tx] = (k < K && n < N) ? W[(long long)k * N + n] : 0.0f;
    }
    __syncthreads();
#pragma unroll
    for (int i = 0; i < 4; i++) {
        int n = nb + ty + i * 8, k = kb + tx;
        if (n < Npad && k < Kpad)
            WT[(long long)n * Kpad + k] = __float2half_rn(tile[tx][ty + i * 8]);
    }
}
// split transpose: W -> WThi + WTlo  (hi = rn(half), lo = rn(half(v - hi)))
__global__ void transpose_half_split_kernel(const float* __restrict__ W,
                                            __half* __restrict__ WThi, __half* __restrict__ WTlo,
                                            int K, int N, int Kpad, int Npad) {
    __shared__ float tile[32][33];
    int kb = blockIdx.x * 32, nb = blockIdx.y * 32;
    int tx = threadIdx.x, ty = threadIdx.y;
#pragma unroll
    for (int i = 0; i < 4; i++) {
        int k = kb + ty + i * 8, n = nb + tx;
        tile[ty + i * 8][tx] = (k < K && n < N) ? W[(long long)k * N + n] : 0.0f;
    }
    __syncthreads();
#pragma unroll
    for (int i = 0; i < 4; i++) {
        int n = nb + ty + i * 8, k = kb + tx;
        if (n < Npad && k < Kpad) {
            float v = tile[tx][ty + i * 8];
            __half h = __float2half_rn(v);
            WThi[(long long)n * Kpad + k] = h;
            WTlo[(long long)n * Kpad + k] = __float2half_rn(v - __half2float(h));
        }
    }
}
// feat -> fhi/flo [NNODES x 512] and fillh rows [0, NNODES)
__global__ void feat_prep_kernel(const float* __restrict__ feat,
                                 __half* __restrict__ fhi, __half* __restrict__ flo,
                                 __half* __restrict__ fillh) {
    long long i = (long long)blockIdx.x * blockDim.x + threadIdx.x;
    if (i >= (long long)NNODES * 512) return;
    int r = (int)(i >> 9), c = (int)(i & 511);
    float v = (c < FEAT) ? feat[(long long)r * FEAT + c] : 0.0f;
    __half h = __float2half_rn(v);
    fhi[i] = h;
    flo[i] = __float2half_rn(v - __half2float(h));
    fillh[i] = h;
}
// znh[r*128+c] = half(z[r*64+c] + noise[r*64+c]) for c<64, else 0
__global__ void add_half_pad_kernel(__half* __restrict__ o, const float* __restrict__ a,
                                    const float* __restrict__ b)
{
    long long i = (long long)blockIdx.x * blockDim.x + threadIdx.x;
    if (i >= (long long)NNODES * 128) return;
    int r = (int)(i >> 7), c = (int)(i & 127);
    o[i] = (c < LAT) ? __float2half_rn(a[(long long)r * LAT + c] + b[(long long)r * LAT + c])
                     : __half(0.0f);
}

// ---------------- fp16 mma GEMM: C[M,N] = A[M,K] @ W[K,N] ------------------
// Single __syncthreads per mainloop iteration (CUTLASS multistage ordering).
// NOTE: requires nChunks >= HSTAGES-1 (K >= 96) for the wait arithmetic.
#define HSTAGES 4
#define H_STRIDE_B 80
#define H_MAT_BYTES (128 * H_STRIDE_B)          // 10240
#define H_STAGE_BYTES (2 * H_MAT_BYTES)         // 20480
#define H_SMEM_TOTAL (HSTAGES * H_STAGE_BYTES)  // 81920

// EPI: 0 none, 1 bias+relu, 2 bias+tanh.  OUT: 0 f32 C, 1 half Ch, 2 f32 C + genh->fillh
// ACC: accumulate into existing f32 C (use with OUT==0)
template <int EPI, int OUT, bool ACC>
__global__ void __launch_bounds__(256, 2) hmma_gemm_kernel(
    const __half* __restrict__ A, const __half* __restrict__ BT,
    const float* __restrict__ bias,
    float* __restrict__ C, __half* __restrict__ Ch,
    int M, int N, int K, int Kpad)
{
    extern __shared__ char smem[];
    const uint32_t sbase = smem_u32(smem);
    const int tid = threadIdx.x;
    const int wid = tid >> 5, lane = tid & 31;
    const int gid = lane >> 2, tig = lane & 3;
    const int warp_m = wid & 3, warp_n = wid >> 2;
    const int m0 = blockIdx.y * 128, n0 = blockIdx.x * 128;

    const int crow = tid >> 1;
    const int cboff = (tid & 1) * 32;

    const __half* aptr;
    {
        int r = m0 + crow;
        int rr = (r < M) ? r : (M - 1);
        aptr = A + (long long)rr * K;
    }
    const __half* bptr = BT + (long long)(n0 + crow) * Kpad;

    const uint32_t sA_wr = sbase + (uint32_t)crow * H_STRIDE_B + (uint32_t)cboff;
    const uint32_t sB_wr = sA_wr + H_MAT_BYTES;

    const int nChunks = K >> 5;

    auto issue = [&](int chunk) {
        int s = chunk & (HSTAGES - 1);
        uint32_t da = sA_wr + (uint32_t)s * H_STAGE_BYTES;
        uint32_t db = sB_wr + (uint32_t)s * H_STAGE_BYTES;
        const char* ga = (const char*)aptr + chunk * 64 + cboff;
        const char* gb = (const char*)bptr + chunk * 64 + cboff;
        CP_ASYNC16(da, ga); CP_ASYNC16(da + 16, ga + 16);
        CP_ASYNC16(db, gb); CP_ASYNC16(db + 16, gb + 16);
        CP_COMMIT();
    };

    float acc[2][8][4];
#pragma unroll
    for (int f = 0; f < 2; f++)
#pragma unroll
        for (int j = 0; j < 8; j++)
#pragma unroll
            for (int q = 0; q < 4; q++) acc[f][j][q] = 0.0f;

    // prologue: HSTAGES-1 real groups (nChunks >= 3 guaranteed by callers)
    for (int s = 0; s < HSTAGES - 1; s++) issue(s);

    uint32_t a_off[2];
#pragma unroll
    for (int f = 0; f < 2; f++) {
        uint32_t row = (uint32_t)(warp_m * 32 + f * 16 + (lane & 15));
        uint32_t colb = (uint32_t)((lane >> 4) << 4);
        a_off[f] = row * H_STRIDE_B + colb;
    }
    uint32_t b_off[4];
#pragma unroll
    for (int jp = 0; jp < 4; jp++) {
        uint32_t row = (uint32_t)(warp_n * 64 + jp * 16 + ((lane >> 4) << 3) + (lane & 7));
        uint32_t colb = (uint32_t)(((lane >> 3) & 1) << 4);
        b_off[jp] = row * H_STRIDE_B + colb;
    }

    // ensure stage 0 ready before first compute
    CP_WAIT(HSTAGES - 2);
    __syncthreads();

    for (int i = 0; i < nChunks; i++) {
        uint32_t sA = sbase + (uint32_t)(i & (HSTAGES - 1)) * H_STAGE_BYTES;
        uint32_t sB = sA + H_MAT_BYTES;
#pragma unroll
        for (int kk = 0; kk < 2; kk++) {
            uint32_t afr[2][4];
            ldsm_x4(sA + a_off[0] + kk * 32, afr[0]);
            ldsm_x4(sA + a_off[1] + kk * 32, afr[1]);
#pragma unroll
            for (int jp = 0; jp < 4; jp++) {
                uint32_t br[4];
                ldsm_x4(sB + b_off[jp] + kk * 32, br);
                mma_f16(acc[0][2 * jp + 0], afr[0], br[0], br[1]);
                mma_f16(acc[1][2 * jp + 0], afr[1], br[0], br[1]);
                mma_f16(acc[0][2 * jp + 1], afr[0], br[2], br[3]);
                mma_f16(acc[1][2 * jp + 1], afr[1], br[2], br[3]);
            }
        }
        if (i + HSTAGES - 1 < nChunks) issue(i + HSTAGES - 1);
        else CP_COMMIT();
        CP_WAIT(HSTAGES - 2);
        __syncthreads();
    }

#pragma unroll
    for (int f = 0; f < 2; f++) {
#pragma unroll
        for (int rr = 0; rr < 2; rr++) {
            int r = m0 + warp_m * 32 + f * 16 + rr * 8 + gid;
            if (r >= M) continue;
#pragma unroll
            for (int j = 0; j < 8; j++) {
                int c = n0 + warp_n * 64 + j * 8 + tig * 2;
                if (c >= N) continue;
                float v0 = acc[f][j][rr * 2 + 0], v1 = acc[f][j][rr * 2 + 1];
                if (ACC) {
                    float2 old = *(const float2*)(C + (long long)r * N + c);
                    v0 += old.x; v1 += old.y;
                }
                if (EPI >= 1) { v0 += bias[c]; v1 += bias[c + 1]; }
                if (EPI == 1) { v0 = fmaxf(v0, 0.f); v1 = fmaxf(v1, 0.f); }
                if (EPI == 2) { v0 = tanhf(v0); v1 = tanhf(v1); }
                if (OUT == 0) {
                    *(float2*)(C + (long long)r * N + c) = make_float2(v0, v1);
                } else if (OUT == 1) {
                    *(__half2*)(Ch + (long long)r * N + c) = __floats2half2_rn(v0, v1);
                } else {
                    *(float2*)(C + (long long)r * N + c) = make_float2(v0, v1);
                    int j5 = c / FEAT, cc = c - j5 * FEAT;
                    *(__half2*)(Ch + ((size_t)(NNODES + r * NPRED + j5) * 512 + cc)) =
                        __floats2half2_rn(v0, v1);
                }
            }
        }
    }
}

// ---------------- SIMT SGEMM (precision-critical GEMM: step 3) ----
#define BM 128
#define BN 128
#define BK 8
__global__ void __launch_bounds__(256, 2) sgemm_kernel(
    const float* __restrict__ A, const float* __restrict__ B,
    float* __restrict__ C, int M, int N, int K)
{
    __shared__ float As[BK][BM];
    __shared__ float Bs[BK][BN];
    const int tid = threadIdx.x;
    const int tx = tid & 15, ty = tid >> 4;
    const int rbase = blockIdx.y * BM, cbase = blockIdx.x * BN;
    float acc[8][8];
#pragma unroll
    for (int i = 0; i < 8; i++)
#pragma unroll
        for (int j = 0; j < 8; j++) acc[i][j] = 0.0f;
    const int arow = tid >> 1, acol = (tid & 1) * 4;
    const int brow = tid >> 5, bcol = (tid & 31) * 4;
    const float* arowptr = (rbase + arow < M) ? A + (long long)(rbase + arow) * K : nullptr;

    for (int kt = 0; kt < K; kt += BK) {
        float4 av = make_float4(0.f, 0.f, 0.f, 0.f);
        if (arowptr) {
            int kc = kt + acol;
            if (kc + 3 < K) av = *(const float4*)(arowptr + kc);
            else {
                if (kc + 0 < K) av.x = arowptr[kc + 0];
                if (kc + 1 < K) av.y = arowptr[kc + 1];
                if (kc + 2 < K) av.z = arowptr[kc + 2];
                if (kc + 3 < K) av.w = arowptr[kc + 3];
            }
        }
        As[acol + 0][arow] = av.x; As[acol + 1][arow] = av.y;
        As[acol + 2][arow] = av.z; As[acol + 3][arow] = av.w;
        float4 bv = make_float4(0.f, 0.f, 0.f, 0.f);
        {
            int kr = kt + brow, cc = cbase + bcol;
            if (kr < K) {
                const float* bp = B + (long long)kr * N + cc;
                if (cc + 3 < N) bv = *(const float4*)bp;
                else {
                    if (cc + 0 < N) bv.x = bp[0];
                    if (cc + 1 < N) bv.y = bp[1];
                    if (cc + 2 < N) bv.z = bp[2];
                    if (cc + 3 < N) bv.w = bp[3];
                }
            }
        }
        *(float4*)&Bs[brow][bcol] = bv;
        __syncthreads();
#pragma unroll
        for (int k = 0; k < BK; k++) {
            float ra[8], rb[8];
            *(float4*)&ra[0] = *(const float4*)&As[k][ty * 4];
            *(float4*)&ra[4] = *(const float4*)&As[k][64 + ty * 4];
            *(float4*)&rb[0] = *(const float4*)&Bs[k][tx * 4];
            *(float4*)&rb[4] = *(const float4*)&Bs[k][64 + tx * 4];
#pragma unroll
            for (int i = 0; i < 8; i++)
#pragma unroll
                for (int j = 0; j < 8; j++) acc[i][j] += ra[i] * rb[j];
        }
        __syncthreads();
    }
#pragma unroll
    for (int i = 0; i < 8; i++) {
        int r = rbase + ((i < 4) ? (ty * 4 + i) : (64 + ty * 4 + i - 4));
        if (r >= M) continue;
#pragma unroll
        for (int j = 0; j < 8; j++) {
            int c = cbase + ((j < 4) ? (tx * 4 + j) : (64 + tx * 4 + j - 4));
            if (c >= N) continue;
            C[(long long)r * N + c] = acc[i][j];
        }
    }
}

// ---------------- skinny GEMM for gc4 ----------------
__global__ void skinny16_kernel(const float* __restrict__ X, const float* __restrict__ W,
                                float* __restrict__ C, int M)
{
    __shared__ float Ws[256 * 16];
    int tid = threadIdx.x;   // 128
    for (int i = tid; i < 256 * 16; i += 128) Ws[i] = W[i];
    __syncthreads();
    int r = blockIdx.x * 128 + tid;
    if (r >= M) return;
    const float* x = X + (long long)r * 256;
    float acc[16];
#pragma unroll
    for (int q = 0; q < 16; q++) acc[q] = 0.0f;
    for (int k = 0; k < 256; k += 4) {
        float4 a = *(const float4*)(x + k);
#pragma unroll
        for (int q = 0; q < 16; q++)
            acc[q] += a.x * Ws[(k + 0) * 16 + q] + a.y * Ws[(k + 1) * 16 + q]
                    + a.z * Ws[(k + 2) * 16 + q] + a.w * Ws[(k + 3) * 16 + q];
    }
    float* co = C + (long long)r * 16;
#pragma unroll
    for (int q = 0; q < 16; q += 4)
        *(float4*)(co + q) = make_float4(acc[q], acc[q + 1], acc[q + 2], acc[q + 3]);
}

// ---------------- misc ----------------
__global__ void degree_kernel(const float* __restrict__ z, const float* __restrict__ Wr,
                              const float* __restrict__ br, float* __restrict__ deg_out,
                              int* __restrict__ pdeg, int n)
{
    int r = blockIdx.x * (blockDim.x >> 5) + (threadIdx.x >> 5);
    int lane = threadIdx.x & 31;
    if (r >= n) return;
    float s = z[(long long)r * LAT + lane] * Wr[lane]
            + z[(long long)r * LAT + 32 + lane] * Wr[32 + lane];
#pragma unroll
    for (int o = 16; o; o >>= 1) s += __shfl_xor_sync(0xffffffffu, s, o);
    if (lane == 0) {
        float d = fmaxf(s + br[0], 0.0f);
        deg_out[r] = d;
        int pi = (int)d;
        if (pi > NPRED) pi = NPRED;
        pdeg[r] = pi;
    }
}

// ---------------- host ----------------
static inline int cdiv(long long a, long long b) { return (int)((a + b - 1) / b); }

extern "C" void kernel_launch(void* const* d_in, const int* in_sizes, int n_in,
                              void* d_out, int out_size)
{
    const float* feat     = (const float*)d_in[0];
    const void*  edges    = d_in[1];
    const void*  adj_rows = d_in[2];
    const void*  adj_cols = d_in[3];
    const float* adj_vals = (const float*)d_in[4];
    const float* noise    = (const float*)d_in[5];
    const float* W_gc1 = (const float*)d_in[6];   const float* b_gc1 = (const float*)d_in[7];
    const float* W_gc2 = (const float*)d_in[8];   const float* b_gc2 = (const float*)d_in[9];
    const float* W_reg = (const float*)d_in[10];  const float* b_reg = (const float*)d_in[11];
    const float* W_fc1 = (const float*)d_in[12];  const float* b_fc1 = (const float*)d_in[13];
    const float* W_fc2 = (const float*)d_in[14];  const float* b_fc2 = (const float*)d_in[15];
    const float* W_flat = (const float*)d_in[16]; const float* b_flat = (const float*)d_in[17];
    const float* W_gc3 = (const float*)d_in[18];  const float* b_gc3 = (const float*)d_in[19];
    const float* W_gc4 = (const float*)d_in[20];  const float* b_gc4 = (const float*)d_in[21];

    float* out = (float*)d_out;
    float* out_deg = out;
    float* out_gen = out + OUT_GEN_OFF;
    float* out_nc  = out + OUT_NC_OFF;

    const long long nnz_adj = in_sizes[2];
    const int E = in_sizes[1] / 2;

    void* p;
    float *bufA, *bufB, *z, *c7;
    __half *g1h, *g2h, *fillh, *fhi, *flo, *znh;
    __half *wh_fc2, *wh_flat, *wh_gc3, *wh_fc1, *whi_gc1, *wlo_gc1;
    int *pdeg, *cnt, *fill, *off_enc, *off_mend, *ecol, *mcol;
    float *eval;
    cudaGetSymbolAddress(&p, g_bufA);  bufA  = (float*)p;
    cudaGetSymbolAddress(&p, g_bufB);  bufB  = (float*)p;
    cudaGetSymbolAddress(&p, g_z);     z     = (float*)p;
    cudaGetSymbolAddress(&p, g_c7);    c7    = (float*)p;
    cudaGetSymbolAddress(&p, g_pdeg);  pdeg  = (int*)p;
    cudaGetSymbolAddress(&p, g_cnt);   cnt   = (int*)p;
    cudaGetSymbolAddress(&p, g_fill);  fill  = (int*)p;
    cudaGetSymbolAddress(&p, g_off_enc);  off_enc  = (int*)p;
    cudaGetSymbolAddress(&p, g_off_mend); off_mend = (int*)p;
    cudaGetSymbolAddress(&p, g_ecol);  ecol  = (int*)p;
    cudaGetSymbolAddress(&p, g_eval);  eval  = (float*)p;
    cudaGetSymbolAddress(&p, g_mcol);  mcol  = (int*)p;
    cudaGetSymbolAddress(&p, g_g1h);   g1h   = (__half*)p;
    cudaGetSymbolAddress(&p, g_g2h);   g2h   = (__half*)p;
    cudaGetSymbolAddress(&p, g_fillh); fillh = (__half*)p;
    cudaGetSymbolAddress(&p, g_fhi);   fhi   = (__half*)p;
    cudaGetSymbolAddress(&p, g_flo);   flo   = (__half*)p;
    cudaGetSymbolAddress(&p, g_znh);   znh   = (__half*)p;
    cudaGetSymbolAddress(&p, g_wh_fc2);  wh_fc2  = (__half*)p;
    cudaGetSymbolAddress(&p, g_wh_flat); wh_flat = (__half*)p;
    cudaGetSymbolAddress(&p, g_wh_gc3);  wh_gc3  = (__half*)p;
    cudaGetSymbolAddress(&p, g_wh_fc1);  wh_fc1  = (__half*)p;
    cudaGetSymbolAddress(&p, g_whi_gc1); whi_gc1 = (__half*)p;
    cudaGetSymbolAddress(&p, g_wlo_gc1); wlo_gc1 = (__half*)p;

    cudaFuncSetAttribute((const void*)hmma_gemm_kernel<0, 0, false>,
                         cudaFuncAttributeMaxDynamicSharedMemorySize, H_SMEM_TOTAL);
    cudaFuncSetAttribute((const void*)hmma_gemm_kernel<0, 0, true>,
                         cudaFuncAttributeMaxDynamicSharedMemorySize, H_SMEM_TOTAL);
    cudaFuncSetAttribute((const void*)hmma_gemm_kernel<1, 1, false>,
                         cudaFuncAttributeMaxDynamicSharedMemorySize, H_SMEM_TOTAL);
    cudaFuncSetAttribute((const void*)hmma_gemm_kernel<2, 2, false>,
                         cudaFuncAttributeMaxDynamicSharedMemorySize, H_SMEM_TOTAL);

    const int TB = 256;
    dim3 tblk(32, 8);

    // 0) prep
    detect_idx_kernel<<<1, 32>>>(adj_rows);
    transpose_half_kernel<<<dim3(cdiv(256, 32), cdiv(2048, 32)), tblk>>>(W_fc2, wh_fc2, 256, 2048, 256, 2048);
    transpose_half_kernel<<<dim3(cdiv(2048, 32), cdiv(2560, 32)), tblk>>>(W_flat, wh_flat, 2048, 2500, 2048, 2560);
    transpose_half_kernel<<<dim3(cdiv(512, 32), cdiv(256, 32)), tblk>>>(W_gc3, wh_gc3, 500, 256, 512, 256);
    transpose_half_kernel<<<dim3(cdiv(128, 32), cdiv(256, 32)), tblk>>>(W_fc1, wh_fc1, 64, 256, 128, 256);
    transpose_half_split_kernel<<<dim3(cdiv(512, 32), cdiv(256, 32)), tblk>>>(W_gc1, whi_gc1, wlo_gc1, 500, 256, 512, 256);
    feat_prep_kernel<<<cdiv((long long)NNODES * 512, TB), TB>>>(feat, fhi, flo, fillh);

    // 0b) encoder CSR build
    cudaMemsetAsync(cnt, 0, NNODES * sizeof(int));
    enc_hist_kernel<<<cdiv(nnz_adj, TB), TB>>>(adj_rows, nnz_adj);
    scan_kernel<<<1, 1024>>>(cnt, off_enc, fill, NNODES);
    enc_fill_kernel<<<cdiv(nnz_adj, TB), TB>>>(adj_rows, adj_cols, adj_vals, nnz_adj);

    // 1) XW1 = feat @ W_gc1 — fp16 split-3 (fp32-class; protects int(degree) cliff)
    {
        dim3 grid(HID / 128, cdiv(NNODES, 128));
        hmma_gemm_kernel<0, 0, false><<<grid, 256, H_SMEM_TOTAL>>>(
            fhi, whi_gc1, nullptr, bufA, nullptr, NNODES, HID, 512, 512);
        hmma_gemm_kernel<0, 0, true><<<grid, 256, H_SMEM_TOTAL>>>(
            fhi, wlo_gc1, nullptr, bufA, nullptr, NNODES, HID, 512, 512);
        hmma_gemm_kernel<0, 0, true><<<grid, 256, H_SMEM_TOTAL>>>(
            flo, whi_gc1, nullptr, bufA, nullptr, NNODES, HID, 512, 512);
    }
    // 2) h = relu(spmm + b1) — CSR gather
    spmm_gather_kernel<256, false><<<cdiv(NNODES, 8), TB>>>(off_enc, ecol, eval, bufA, b_gc1, bufB, NNODES);
    // 3) hW2 = h @ W_gc2 — fp32 exact
    {
        dim3 grid(cdiv(LAT, BN), cdiv(NNODES, BM));
        sgemm_kernel<<<grid, TB>>>(bufB, W_gc2, bufA, NNODES, LAT, HID);
    }
    // 4) z = relu(spmm + b2)
    spmm_gather_kernel<64, false><<<cdiv(NNODES, 8), TB>>>(off_enc, ecol, eval, bufA, b_gc2, z, NNODES);
    // 5) degree + pred_deg
    degree_kernel<<<cdiv(NNODES, TB / 32), TB>>>(z, W_reg, b_reg, out_deg, pdeg, NNODES);
    // 5b) mend CSR build
    cudaMemsetAsync(cnt, 0, NODE_LEN * sizeof(int));
    mend_hist_edges_kernel<<<cdiv(E, TB), TB>>>(edges, E);
    mend_hist_new_kernel<<<cdiv(NNODES * NPRED, TB), TB>>>(pdeg);
    scan_kernel<<<1, 1024>>>(cnt, off_mend, fill, NODE_LEN);
    mend_fill_edges_kernel<<<cdiv(E, TB), TB>>>(edges, E);
    mend_fill_new_kernel<<<cdiv(NNODES * NPRED, TB), TB>>>(pdeg);
    // 6) znh = half(z + noise), zero-padded to K=128 (removes K=64 pipeline race)
    add_half_pad_kernel<<<cdiv((long long)NNODES * 128, TB), TB>>>(znh, z, noise);
    // 7) g1h = half(relu(znh @ W_fc1 + b)) — fp16 mma (K=128 padded)
    {
        dim3 grid(FC1N / 128, cdiv(NNODES, 128));
        hmma_gemm_kernel<1, 1, false><<<grid, 256, H_SMEM_TOTAL>>>(
            znh, wh_fc1, b_fc1, nullptr, g1h, NNODES, FC1N, 128, 128);
    }
    // 8) g2h = half(relu(g1h @ W_fc2 + b)) — fp16 mma
    {
        dim3 grid(FC2N / 128, cdiv(NNODES, 128));
        hmma_gemm_kernel<1, 1, false><<<grid, 256, H_SMEM_TOTAL>>>(
            g1h, wh_fc2, b_fc2, nullptr, g2h, NNODES, FC2N, FC1N, 256);
    }
    // 9) gen_feat = tanh(g2h @ W_flat + b) — fp16 mma; f32 out_gen + half fillh gen rows
    {
        dim3 grid(2560 / 128, cdiv(NNODES, 128));
        hmma_gemm_kernel<2, 2, false><<<grid, 256, H_SMEM_TOTAL>>>(
            g2h, wh_flat, b_flat, out_gen, fillh, NNODES, GENF, FC2N, 2048);
    }
    // 10) fillW3 = fillh @ W_gc3 — fp16 mma (K padded to 512)
    {
        dim3 grid(HID / 128, cdiv(NODE_LEN, 128));
        hmma_gemm_kernel<0, 0, false><<<grid, 256, H_SMEM_TOTAL>>>(
            fillh, wh_gc3, nullptr, bufA, nullptr, NODE_LEN, HID, 512, 512);
    }
    // 12) mend layer 1 — CSR gather, fused normalize+bias+relu
    spmm_gather_kernel<256, true><<<cdiv(NODE_LEN, 8), TB>>>(off_mend, mcol, nullptr, bufA, b_gc3, bufB, NODE_LEN);
    // 13) c7 = h2 @ W_gc4 — skinny N=16
    skinny16_kernel<<<cdiv(NODE_LEN, 128), 128>>>(bufB, W_gc4, c7, NODE_LEN);
    // 14) mend layer 2 — CSR gather
    spmm_gather_kernel<16, true><<<cdiv(NODE_LEN, 8), TB>>>(off_mend, mcol, nullptr, c7, b_gc4, out_nc, NODE_LEN);

    (void)n_in; (void)out_size;
}

// round 13
// speedup vs baseline: 1.3463x; 1.0370x over previous
#include <cuda_runtime.h>
#include <cuda_fp16.h>
#include <cstdint>

// ---------------- problem constants ----------------
#define NNODES   20000
#define FEAT     500
#define HID      256
#define LAT      64
#define NPRED    5
#define NCLS     16
#define NODE_LEN (NNODES + NNODES * NPRED)      // 120000
#define GENF     (NPRED * FEAT)                 // 2500
#define FC1N     256
#define FC2N     2048

#define OUT_GEN_OFF ((long long)NNODES)
#define OUT_NC_OFF  ((long long)NNODES + (long long)NNODES * GENF)

// ---------------- scratch (static device globals; no allocation) ------------
__device__ float g_bufA[(size_t)NODE_LEN * HID];
__device__ float g_bufB[(size_t)NODE_LEN * HID];
__device__ float g_z[(size_t)NNODES * LAT];
__device__ float g_c7[(size_t)NODE_LEN * NCLS];
__device__ int   g_pdeg[NNODES];
__device__ int   g_is64;
// fp16 operands
__device__ __half g_g1h[(size_t)NNODES * FC1N];
__device__ __half g_g2h[(size_t)NNODES * FC2N];
__device__ __half g_fillh[(size_t)NODE_LEN * 512];
__device__ __half g_fhi[(size_t)NNODES * 512];
__device__ __half g_flo[(size_t)NNODES * 512];
__device__ __half g_hhi[(size_t)NNODES * 256];
__device__ __half g_hlo[(size_t)NNODES * 256];
__device__ __half g_znh[(size_t)NNODES * 128];
__device__ __half g_wh_fc2[(size_t)2048 * 256];
__device__ __half g_wh_flat[(size_t)2560 * 2048];
__device__ __half g_wh_gc3[(size_t)256 * 512];
__device__ __half g_wh_fc1[(size_t)256 * 128];
__device__ __half g_whi_gc1[(size_t)256 * 512];
__device__ __half g_wlo_gc1[(size_t)256 * 512];
__device__ __half g_whi_gc2[(size_t)128 * 256];
__device__ __half g_wlo_gc2[(size_t)128 * 256];
// CSR scratch
__device__ int   g_cnt[NODE_LEN];
__device__ int   g_fill[NODE_LEN];
__device__ int   g_off_enc[NNODES + 1];
__device__ int   g_off_mend[NODE_LEN + 1];
__device__ int   g_ecol[700000];
__device__ float g_eval[700000];
__device__ int   g_mcol[900000];

// ---------------- helpers ----------------
__device__ __forceinline__ uint32_t smem_u32(const void* p) {
    uint32_t a;
    asm("{ .reg .u64 t; cvta.to.shared.u64 t, %1; cvt.u32.u64 %0, t; }" : "=r"(a) : "l"(p));
    return a;
}
__device__ __forceinline__ void ldsm_x4(uint32_t addr, uint32_t* r) {
    asm volatile("ldmatrix.sync.aligned.m8n8.x4.shared.b16 {%0,%1,%2,%3}, [%4];"
                 : "=r"(r[0]), "=r"(r[1]), "=r"(r[2]), "=r"(r[3]) : "r"(addr));
}
__device__ __forceinline__ void mma_f16(float* c, const uint32_t* a, uint32_t b0, uint32_t b1) {
    asm volatile(
        "mma.sync.aligned.m16n8k16.row.col.f32.f16.f16.f32 "
        "{%0,%1,%2,%3}, {%4,%5,%6,%7}, {%8,%9}, {%0,%1,%2,%3};"
        : "+f"(c[0]), "+f"(c[1]), "+f"(c[2]), "+f"(c[3])
        : "r"(a[0]), "r"(a[1]), "r"(a[2]), "r"(a[3]), "r"(b0), "r"(b1));
}
#define CP_ASYNC16(dst, src) \
    asm volatile("cp.async.cg.shared.global [%0], [%1], 16;" :: "r"(dst), "l"(src))
#define CP_COMMIT() asm volatile("cp.async.commit_group;" ::: "memory")
#define CP_WAIT(n)  asm volatile("cp.async.wait_group %0;" :: "n"(n) : "memory")

// ---------------- index dtype detection ----------------
__global__ void detect_idx_kernel(const void* adj_rows) {
    int lane = threadIdx.x;
    const long long* p = (const long long*)adj_rows;
    int bad = 0;
    for (int i = lane; i < 256; i += 32) {
        long long v = p[i];
        if (v < 0 || v >= NODE_LEN) bad = 1;
    }
    unsigned m = __ballot_sync(0xffffffffu, bad);
    if (lane == 0) g_is64 = (m == 0) ? 1 : 0;
}
__device__ __forceinline__ long long load_idx(const void* p, long long i) {
    return g_is64 ? ((const long long*)p)[i] : (long long)((const int*)p)[i];
}

// ---------------- CSR build ----------------
__global__ void enc_hist_kernel(const void* __restrict__ rows, long long nnz) {
    long long e = (long long)blockIdx.x * blockDim.x + threadIdx.x;
    if (e >= nnz) return;
    atomicAdd(&g_cnt[load_idx(rows, e)], 1);
}
__global__ void enc_fill_kernel(const void* __restrict__ rows, const void* __restrict__ cols,
                                const float* __restrict__ vals, long long nnz) {
    long long e = (long long)blockIdx.x * blockDim.x + threadIdx.x;
    if (e >= nnz) return;
    int r = (int)load_idx(rows, e);
    int pos = atomicAdd(&g_fill[r], 1);
    g_ecol[pos] = (int)load_idx(cols, e);
    g_eval[pos] = vals[e];
}
__global__ void scan_kernel(const int* __restrict__ cnt, int* __restrict__ off,
                            int* __restrict__ fill, int n) {
    __shared__ int part[1024];
    int t = threadIdx.x;
    int chunk = (n + 1023) >> 10;
    int lo = t * chunk, hi = lo + chunk;
    if (hi > n) hi = n;
    int s = 0;
    for (int i = lo; i < hi; i++) s += cnt[i];
    part[t] = s;
    __syncthreads();
    for (int d = 1; d < 1024; d <<= 1) {
        int add = (t >= d) ? part[t - d] : 0;
        __syncthreads();
        part[t] += add;
        __syncthreads();
    }
    int run = part[t] - s;
    for (int i = lo; i < hi; i++) {
        off[i] = run; fill[i] = run;
        run += cnt[i];
    }
    if (t == 1023) off[n] = part[1023];
}
__global__ void mend_hist_edges_kernel(const void* __restrict__ edges, int E) {
    int e = blockIdx.x * blockDim.x + threadIdx.x;
    if (e >= E) return;
    int lo = (int)load_idx(edges, 2LL * e);
    int hi = (int)load_idx(edges, 2LL * e + 1);
    atomicAdd(&g_cnt[lo], 1);
    atomicAdd(&g_cnt[hi], 1);
}
__global__ void mend_hist_new_kernel(const int* __restrict__ pdeg) {
    int t = blockIdx.x * blockDim.x + threadIdx.x;
    if (t >= NNODES * NPRED) return;
    int node = t / NPRED, j = t - node * NPRED;
    if (j < pdeg[node]) {
        atomicAdd(&g_cnt[node], 1);
        g_cnt[NNODES + t] = 1;
    }
}
__global__ void mend_fill_edges_kernel(const void* __restrict__ edges, int E) {
    int e = blockIdx.x * blockDim.x + threadIdx.x;
    if (e >= E) return;
    int lo = (int)load_idx(edges, 2LL * e);
    int hi = (int)load_idx(edges, 2LL * e + 1);
    int p0 = atomicAdd(&g_fill[lo], 1);
    g_mcol[p0] = hi;
    int p1 = atomicAdd(&g_fill[hi], 1);
    g_mcol[p1] = lo;
}
__global__ void mend_fill_new_kernel(const int* __restrict__ pdeg) {
    int t = blockIdx.x * blockDim.x + threadIdx.x;
    if (t >= NNODES * NPRED) return;
    int node = t / NPRED, j = t - node * NPRED;
    if (j < pdeg[node]) {
        int p0 = atomicAdd(&g_fill[node], 1);
        g_mcol[p0] = NNODES + t;
        g_mcol[g_off_mend[NNODES + t]] = node;
    }
}

// ---------------- gather SpMM (warp per row) ----------------
template <int D, bool MEND>
__global__ void spmm_gather_kernel(const int* __restrict__ off, const int* __restrict__ cols,
                                   const float* __restrict__ vals,
                                   const float* __restrict__ x, const float* __restrict__ bias,
                                   float* __restrict__ y, int nrows)
{
    int w = (int)(((long long)blockIdx.x * blockDim.x + threadIdx.x) >> 5);
    int lane = threadIdx.x & 31;
    if (w >= nrows) return;
    int e0 = off[w], e1 = off[w + 1];

    if (D == 256) {
        float a[8] = {0, 0, 0, 0, 0, 0, 0, 0};
        const int cb = lane * 4;
        for (int e = e0; e < e1; e++) {
            long long c = cols[e];
            float4 t0 = *(const float4*)(x + c * 256 + cb);
            float4 t1 = *(const float4*)(x + c * 256 + 128 + cb);
            a[0] += t0.x; a[1] += t0.y; a[2] += t0.z; a[3] += t0.w;
            a[4] += t1.x; a[5] += t1.y; a[6] += t1.z; a[7] += t1.w;
        }
        float4 o0, o1;
        float inv = 1.0f / (1.0f + (float)(e1 - e0));
        const float* xr = x + (long long)w * 256;
        o0.x = fmaxf((a[0] + xr[cb + 0]) * inv + bias[cb + 0], 0.f);
        o0.y = fmaxf((a[1] + xr[cb + 1]) * inv + bias[cb + 1], 0.f);
        o0.z = fmaxf((a[2] + xr[cb + 2]) * inv + bias[cb + 2], 0.f);
        o0.w = fmaxf((a[3] + xr[cb + 3]) * inv + bias[cb + 3], 0.f);
        o1.x = fmaxf((a[4] + xr[128 + cb + 0]) * inv + bias[128 + cb + 0], 0.f);
        o1.y = fmaxf((a[5] + xr[128 + cb + 1]) * inv + bias[128 + cb + 1], 0.f);
        o1.z = fmaxf((a[6] + xr[128 + cb + 2]) * inv + bias[128 + cb + 2], 0.f);
        o1.w = fmaxf((a[7] + xr[128 + cb + 3]) * inv + bias[128 + cb + 3], 0.f);
        *(float4*)(y + (long long)w * 256 + cb) = o0;
        *(float4*)(y + (long long)w * 256 + 128 + cb) = o1;
    } else if (D == 64) {
        float a0 = 0.f, a1 = 0.f;
        const int cb = lane * 2;
        for (int e = e0; e < e1; e++) {
            long long c = cols[e];
            float2 t = *(const float2*)(x + c * 64 + cb);
            float v = vals[e];
            a0 += v * t.x; a1 += v * t.y;
        }
        float2 o;
        o.x = fmaxf(a0 + bias[cb + 0], 0.f);
        o.y = fmaxf(a1 + bias[cb + 1], 0.f);
        *(float2*)(y + (long long)w * 64 + cb) = o;
    } else {  // D == 16, MEND
        if (lane < 16) {
            float a = 0.f;
            for (int e = e0; e < e1; e++)
                a += x[(long long)cols[e] * 16 + lane];
            float inv = 1.0f / (1.0f + (float)(e1 - e0));
            float v = (a + x[(long long)w * 16 + lane]) * inv + bias[lane];
            y[(long long)w * 16 + lane] = fmaxf(v, 0.f);
        }
    }
}

// encoder gather D=256 writing split fp16 (hi, lo) — feeds split-3 GEMM step 3
__global__ void spmm_gather_split_kernel(const int* __restrict__ off, const int* __restrict__ cols,
                                         const float* __restrict__ vals,
                                         const float* __restrict__ x, const float* __restrict__ bias,
                                         __half* __restrict__ yhi, __half* __restrict__ ylo, int nrows)
{
    int w = (int)(((long long)blockIdx.x * blockDim.x + threadIdx.x) >> 5);
    int lane = threadIdx.x & 31;
    if (w >= nrows) return;
    int e0 = off[w], e1 = off[w + 1];
    float a[8] = {0, 0, 0, 0, 0, 0, 0, 0};
    const int cb = lane * 4;
    for (int e = e0; e < e1; e++) {
        long long c = cols[e];
        float4 t0 = *(const float4*)(x + c * 256 + cb);
        float4 t1 = *(const float4*)(x + c * 256 + 128 + cb);
        float v = vals[e];
        a[0] += v * t0.x; a[1] += v * t0.y; a[2] += v * t0.z; a[3] += v * t0.w;
        a[4] += v * t1.x; a[5] += v * t1.y; a[6] += v * t1.z; a[7] += v * t1.w;
    }
#pragma unroll
    for (int g = 0; g < 2; g++) {
        int base = g * 128 + cb;
        float v0 = fmaxf(a[4 * g + 0] + bias[base + 0], 0.f);
        float v1 = fmaxf(a[4 * g + 1] + bias[base + 1], 0.f);
        float v2 = fmaxf(a[4 * g + 2] + bias[base + 2], 0.f);
        float v3 = fmaxf(a[4 * g + 3] + bias[base + 3], 0.f);
        __half h0 = __float2half_rn(v0), h1 = __float2half_rn(v1);
        __half h2 = __float2half_rn(v2), h3 = __float2half_rn(v3);
        long long o = (long long)w * 256 + base;
        *(__half2*)(yhi + o)     = __halves2half2(h0, h1);
        *(__half2*)(yhi + o + 2) = __halves2half2(h2, h3);
        *(__half2*)(ylo + o)     = __halves2half2(__float2half_rn(v0 - __half2float(h0)),
                                                  __float2half_rn(v1 - __half2float(h1)));
        *(__half2*)(ylo + o + 2) = __halves2half2(__float2half_rn(v2 - __half2float(h2)),
                                                  __float2half_rn(v3 - __half2float(h3)));
    }
}

// ---------------- weight transpose -> half: W[K,N] -> WT[Npad,Kpad] --------
__global__ void transpose_half_kernel(const float* __restrict__ W, __half* __restrict__ WT,
                                      int K, int N, int Kpad, int Npad) {
    __shared__ float tile[32][33];
    int kb = blockIdx.x * 32, nb = blockIdx.y * 32;
    int tx = threadIdx.x, ty = threadIdx.y;   // 32 x 8
#pragma unroll
    for (int i = 0; i < 4; i++) {
        int k = kb + ty + i * 8, n = nb + tx;
        tile[ty + i * 8][tx] = (k < K && n < N) ? W[(long long)k * N + n] : 0.0f;
    }
    __syncthreads();
#pragma unroll
    for (int i = 0; i < 4; i++) {
        int n = nb + ty + i * 8, k = kb + tx;
        if (n < Npad && k < Kpad)
            WT[(long long)n * Kpad + k] = __float2half_rn(tile[tx][ty + i * 8]);
    }
}
// split transpose: W -> WThi + WTlo
__global__ void transpose_half_split_kernel(const float* __restrict__ W,
                                            __half* __restrict__ WThi, __half* __restrict__ WTlo,
                                            int K, int N, int Kpad, int Npad) {
    __shared__ float tile[32][33];
    int kb = blockIdx.x * 32, nb = blockIdx.y * 32;
    int tx = threadIdx.x, ty = threadIdx.y;
#pragma unroll
    for (int i = 0; i < 4; i++) {
        int k = kb + ty + i * 8, n = nb + tx;
        tile[ty + i * 8][tx] = (k < K && n < N) ? W[(long long)k * N + n] : 0.0f;
    }
    __syncthreads();
#pragma unroll
    for (int i = 0; i < 4; i++) {
        int n = nb + ty + i * 8, k = kb + tx;
        if (n < Npad && k < Kpad) {
            float v = tile[tx][ty + i * 8];
            __half h = __float2half_rn(v);
            WThi[(long long)n * Kpad + k] = h;
            WTlo[(long long)n * Kpad + k] = __float2half_rn(v - __half2float(h));
        }
    }
}
// feat -> fhi/flo [NNODES x 512] and fillh rows [0, NNODES)
__global__ void feat_prep_kernel(const float* __restrict__ feat,
                                 __half* __restrict__ fhi, __half* __restrict__ flo,
                                 __half* __restrict__ fillh) {
    long long i = (long long)blockIdx.x * blockDim.x + threadIdx.x;
    if (i >= (long long)NNODES * 512) return;
    int r = (int)(i >> 9), c = (int)(i & 511);
    float v = (c < FEAT) ? feat[(long long)r * FEAT + c] : 0.0f;
    __half h = __float2half_rn(v);
    fhi[i] = h;
    flo[i] = __float2half_rn(v - __half2float(h));
    fillh[i] = h;
}
// znh[r*128+c] = half(z[r*64+c] + noise[r*64+c]) for c<64, else 0
__global__ void add_half_pad_kernel(__half* __restrict__ o, const float* __restrict__ a,
                                    const float* __restrict__ b)
{
    long long i = (long long)blockIdx.x * blockDim.x + threadIdx.x;
    if (i >= (long long)NNODES * 128) return;
    int r = (int)(i >> 7), c = (int)(i & 127);
    o[i] = (c < LAT) ? __float2half_rn(a[(long long)r * LAT + c] + b[(long long)r * LAT + c])
                     : __half(0.0f);
}

// ---------------- fp16 mma GEMM ------------------
#define HSTAGES 4
#define H_STRIDE_B 80
#define H_MAT_BYTES (128 * H_STRIDE_B)          // 10240
#define H_STAGE_BYTES (2 * H_MAT_BYTES)         // 20480
#define H_SMEM_TOTAL (HSTAGES * H_STAGE_BYTES)  // 81920

// EPI: 0 none, 1 bias+relu, 2 bias+tanh.  OUT: 0 f32 C, 1 half Ch, 2 f32 C + genh->fillh
template <int EPI, int OUT>
__global__ void __launch_bounds__(256, 2) hmma_gemm_kernel(
    const __half* __restrict__ A, const __half* __restrict__ BT,
    const float* __restrict__ bias,
    float* __restrict__ C, __half* __restrict__ Ch,
    int M, int N, int K, int Kpad)
{
    extern __shared__ char smem[];
    const uint32_t sbase = smem_u32(smem);
    const int tid = threadIdx.x;
    const int wid = tid >> 5, lane = tid & 31;
    const int gid = lane >> 2, tig = lane & 3;
    const int warp_m = wid & 3, warp_n = wid >> 2;
    const int m0 = blockIdx.y * 128, n0 = blockIdx.x * 128;

    const int crow = tid >> 1;
    const int cboff = (tid & 1) * 32;

    const __half* aptr;
    {
        int r = m0 + crow;
        int rr = (r < M) ? r : (M - 1);
        aptr = A + (long long)rr * K;
    }
    const __half* bptr = BT + (long long)(n0 + crow) * Kpad;

    const uint32_t sA_wr = sbase + (uint32_t)crow * H_STRIDE_B + (uint32_t)cboff;
    const uint32_t sB_wr = sA_wr + H_MAT_BYTES;

    const int nChunks = K >> 5;

    auto issue = [&](int chunk) {
        int s = chunk & (HSTAGES - 1);
        uint32_t da = sA_wr + (uint32_t)s * H_STAGE_BYTES;
        uint32_t db = sB_wr + (uint32_t)s * H_STAGE_BYTES;
        const char* ga = (const char*)aptr + chunk * 64 + cboff;
        const char* gb = (const char*)bptr + chunk * 64 + cboff;
        CP_ASYNC16(da, ga); CP_ASYNC16(da + 16, ga + 16);
        CP_ASYNC16(db, gb); CP_ASYNC16(db + 16, gb + 16);
        CP_COMMIT();
    };

    float acc[2][8][4];
#pragma unroll
    for (int f = 0; f < 2; f++)
#pragma unroll
        for (int j = 0; j < 8; j++)
#pragma unroll
            for (int q = 0; q < 4; q++) acc[f][j][q] = 0.0f;

    for (int s = 0; s < HSTAGES - 1; s++) issue(s);

    uint32_t a_off[2];
#pragma unroll
    for (int f = 0; f < 2; f++) {
        uint32_t row = (uint32_t)(warp_m * 32 + f * 16 + (lane & 15));
        uint32_t colb = (uint32_t)((lane >> 4) << 4);
        a_off[f] = row * H_STRIDE_B + colb;
    }
    uint32_t b_off[4];
#pragma unroll
    for (int jp = 0; jp < 4; jp++) {
        uint32_t row = (uint32_t)(warp_n * 64 + jp * 16 + ((lane >> 4) << 3) + (lane & 7));
        uint32_t colb = (uint32_t)(((lane >> 3) & 1) << 4);
        b_off[jp] = row * H_STRIDE_B + colb;
    }

    CP_WAIT(HSTAGES - 2);
    __syncthreads();

    for (int i = 0; i < nChunks; i++) {
        uint32_t sA = sbase + (uint32_t)(i & (HSTAGES - 1)) * H_STAGE_BYTES;
        uint32_t sB = sA + H_MAT_BYTES;
#pragma unroll
        for (int kk = 0; kk < 2; kk++) {
            uint32_t afr[2][4];
            ldsm_x4(sA + a_off[0] + kk * 32, afr[0]);
            ldsm_x4(sA + a_off[1] + kk * 32, afr[1]);
#pragma unroll
            for (int jp = 0; jp < 4; jp++) {
                uint32_t br[4];
                ldsm_x4(sB + b_off[jp] + kk * 32, br);
                mma_f16(acc[0][2 * jp + 0], afr[0], br[0], br[1]);
                mma_f16(acc[1][2 * jp + 0], afr[1], br[0], br[1]);
                mma_f16(acc[0][2 * jp + 1], afr[0], br[2], br[3]);
                mma_f16(acc[1][2 * jp + 1], afr[1], br[2], br[3]);
            }
        }
        if (i + HSTAGES - 1 < nChunks) issue(i + HSTAGES - 1);
        else CP_COMMIT();
        CP_WAIT(HSTAGES - 2);
        __syncthreads();
    }

#pragma unroll
    for (int f = 0; f < 2; f++) {
#pragma unroll
        for (int rr = 0; rr < 2; rr++) {
            int r = m0 + warp_m * 32 + f * 16 + rr * 8 + gid;
            if (r >= M) continue;
#pragma unroll
            for (int j = 0; j < 8; j++) {
                int c = n0 + warp_n * 64 + j * 8 + tig * 2;
                if (c >= N) continue;
                float v0 = acc[f][j][rr * 2 + 0], v1 = acc[f][j][rr * 2 + 1];
                if (EPI >= 1) { v0 += bias[c]; v1 += bias[c + 1]; }
                if (EPI == 1) { v0 = fmaxf(v0, 0.f); v1 = fmaxf(v1, 0.f); }
                if (EPI == 2) { v0 = tanhf(v0); v1 = tanhf(v1); }
                if (OUT == 0) {
                    *(float2*)(C + (long long)r * N + c) = make_float2(v0, v1);
                } else if (OUT == 1) {
                    *(__half2*)(Ch + (long long)r * N + c) = __floats2half2_rn(v0, v1);
                } else {
                    *(float2*)(C + (long long)r * N + c) = make_float2(v0, v1);
                    int j5 = c / FEAT, cc = c - j5 * FEAT;
                    *(__half2*)(Ch + ((size_t)(NNODES + r * NPRED + j5) * 512 + cc)) =
                        __floats2half2_rn(v0, v1);
                }
            }
        }
    }
}

// ---------------- triple-pass split-3 GEMM: C = A0@B0 + A1@B1 + A2@B2 ------
// All K equal; same multistage pipeline, pass index folded into the chunk loop.
__global__ void __launch_bounds__(256, 2) hmma_gemm3_kernel(
    const __half* __restrict__ A0, const __half* __restrict__ A1, const __half* __restrict__ A2,
    const __half* __restrict__ B0, const __half* __restrict__ B1, const __half* __restrict__ B2,
    float* __restrict__ C, int M, int N, int K, int Kpad)
{
    extern __shared__ char smem[];
    const uint32_t sbase = smem_u32(smem);
    const int tid = threadIdx.x;
    const int wid = tid >> 5, lane = tid & 31;
    const int gid = lane >> 2, tig = lane & 3;
    const int warp_m = wid & 3, warp_n = wid >> 2;
    const int m0 = blockIdx.y * 128, n0 = blockIdx.x * 128;

    const int crow = tid >> 1;
    const int cboff = (tid & 1) * 32;

    int rr = (m0 + crow < M) ? (m0 + crow) : (M - 1);
    const __half* ap0 = A0 + (long long)rr * K;
    const __half* ap1 = A1 + (long long)rr * K;
    const __half* ap2 = A2 + (long long)rr * K;
    const __half* bp0 = B0 + (long long)(n0 + crow) * Kpad;
    const __half* bp1 = B1 + (long long)(n0 + crow) * Kpad;
    const __half* bp2 = B2 + (long long)(n0 + crow) * Kpad;

    const uint32_t sA_wr = sbase + (uint32_t)crow * H_STRIDE_B + (uint32_t)cboff;
    const uint32_t sB_wr = sA_wr + H_MAT_BYTES;

    const int nChunks = K >> 5;
    const int total = 3 * nChunks;

    auto issue = [&](int t) {
        int pass = t / nChunks;
        int local = t - pass * nChunks;
        const __half* ga = (pass == 0) ? ap0 : (pass == 1) ? ap1 : ap2;
        const __half* gb = (pass == 0) ? bp0 : (pass == 1) ? bp1 : bp2;
        int s = t & (HSTAGES - 1);
        uint32_t da = sA_wr + (uint32_t)s * H_STAGE_BYTES;
        uint32_t db = sB_wr + (uint32_t)s * H_STAGE_BYTES;
        const char* pa = (const char*)ga + local * 64 + cboff;
        const char* pb = (const char*)gb + local * 64 + cboff;
        CP_ASYNC16(da, pa); CP_ASYNC16(da + 16, pa + 16);
        CP_ASYNC16(db, pb); CP_ASYNC16(db + 16, pb + 16);
        CP_COMMIT();
    };

    float acc[2][8][4];
#pragma unroll
    for (int f = 0; f < 2; f++)
#pragma unroll
        for (int j = 0; j < 8; j++)
#pragma unroll
            for (int q = 0; q < 4; q++) acc[f][j][q] = 0.0f;

    for (int s = 0; s < HSTAGES - 1; s++) issue(s);

    uint32_t a_off[2];
#pragma unroll
    for (int f = 0; f < 2; f++) {
        uint32_t row = (uint32_t)(warp_m * 32 + f * 16 + (lane & 15));
        uint32_t colb = (uint32_t)((lane >> 4) << 4);
        a_off[f] = row * H_STRIDE_B + colb;
    }
    uint32_t b_off[4];
#pragma unroll
    for (int jp = 0; jp < 4; jp++) {
        uint32_t row = (uint32_t)(warp_n * 64 + jp * 16 + ((lane >> 4) << 3) + (lane & 7));
        uint32_t colb = (uint32_t)(((lane >> 3) & 1) << 4);
        b_off[jp] = row * H_STRIDE_B + colb;
    }

    CP_WAIT(HSTAGES - 2);
    __syncthreads();

    for (int i = 0; i < total; i++) {
        uint32_t sA = sbase + (uint32_t)(i & (HSTAGES - 1)) * H_STAGE_BYTES;
        uint32_t sB = sA + H_MAT_BYTES;
#pragma unroll
        for (int kk = 0; kk < 2; kk++) {
            uint32_t afr[2][4];
            ldsm_x4(sA + a_off[0] + kk * 32, afr[0]);
            ldsm_x4(sA + a_off[1] + kk * 32, afr[1]);
#pragma unroll
            for (int jp = 0; jp < 4; jp++) {
                uint32_t br[4];
                ldsm_x4(sB + b_off[jp] + kk * 32, br);
                mma_f16(acc[0][2 * jp + 0], afr[0], br[0], br[1]);
                mma_f16(acc[1][2 * jp + 0], afr[1], br[0], br[1]);
                mma_f16(acc[0][2 * jp + 1], afr[0], br[2], br[3]);
                mma_f16(acc[1][2 * jp + 1], afr[1], br[2], br[3]);
            }
        }
        if (i + HSTAGES - 1 < total) issue(i + HSTAGES - 1);
        else CP_COMMIT();
        CP_WAIT(HSTAGES - 2);
        __syncthreads();
    }

#pragma unroll
    for (int f = 0; f < 2; f++) {
#pragma unroll
        for (int rr2 = 0; rr2 < 2; rr2++) {
            int r = m0 + warp_m * 32 + f * 16 + rr2 * 8 + gid;
            if (r >= M) continue;
#pragma unroll
            for (int j = 0; j < 8; j++) {
                int c = n0 + warp_n * 64 + j * 8 + tig * 2;
                if (c >= N) continue;
                *(float2*)(C + (long long)r * N + c) =
                    make_float2(acc[f][j][rr2 * 2 + 0], acc[f][j][rr2 * 2 + 1]);
            }
        }
    }
}

// ---------------- skinny GEMM for gc4 ----------------
__global__ void skinny16_kernel(const float* __restrict__ X, const float* __restrict__ W,
                                float* __restrict__ C, int M)
{
    __shared__ float Ws[256 * 16];
    int tid = threadIdx.x;   // 128
    for (int i = tid; i < 256 * 16; i += 128) Ws[i] = W[i];
    __syncthreads();
    int r = blockIdx.x * 128 + tid;
    if (r >= M) return;
    const float* x = X + (long long)r * 256;
    float acc[16];
#pragma unroll
    for (int q = 0; q < 16; q++) acc[q] = 0.0f;
    for (int k = 0; k < 256; k += 4) {
        float4 a = *(const float4*)(x + k);
#pragma unroll
        for (int q = 0; q < 16; q++)
            acc[q] += a.x * Ws[(k + 0) * 16 + q] + a.y * Ws[(k + 1) * 16 + q]
                    + a.z * Ws[(k + 2) * 16 + q] + a.w * Ws[(k + 3) * 16 + q];
    }
    float* co = C + (long long)r * 16;
#pragma unroll
    for (int q = 0; q < 16; q += 4)
        *(float4*)(co + q) = make_float4(acc[q], acc[q + 1], acc[q + 2], acc[q + 3]);
}

// ---------------- misc ----------------
__global__ void degree_kernel(const float* __restrict__ z, const float* __restrict__ Wr,
                              const float* __restrict__ br, float* __restrict__ deg_out,
                              int* __restrict__ pdeg, int n)
{
    int r = blockIdx.x * (blockDim.x >> 5) + (threadIdx.x >> 5);
    int lane = threadIdx.x & 31;
    if (r >= n) return;
    float s = z[(long long)r * LAT + lane] * Wr[lane]
            + z[(long long)r * LAT + 32 + lane] * Wr[32 + lane];
#pragma unroll
    for (int o = 16; o; o >>= 1) s += __shfl_xor_sync(0xffffffffu, s, o);
    if (lane == 0) {
        float d = fmaxf(s + br[0], 0.0f);
        deg_out[r] = d;
        int pi = (int)d;
        if (pi > NPRED) pi = NPRED;
        pdeg[r] = pi;
    }
}

// ---------------- host ----------------
static inline int cdiv(long long a, long long b) { return (int)((a + b - 1) / b); }

extern "C" void kernel_launch(void* const* d_in, const int* in_sizes, int n_in,
                              void* d_out, int out_size)
{
    const float* feat     = (const float*)d_in[0];
    const void*  edges    = d_in[1];
    const void*  adj_rows = d_in[2];
    const void*  adj_cols = d_in[3];
    const float* adj_vals = (const float*)d_in[4];
    const float* noise    = (const float*)d_in[5];
    const float* W_gc1 = (const float*)d_in[6];   const float* b_gc1 = (const float*)d_in[7];
    const float* W_gc2 = (const float*)d_in[8];   const float* b_gc2 = (const float*)d_in[9];
    const float* W_reg = (const float*)d_in[10];  const float* b_reg = (const float*)d_in[11];
    const float* W_fc1 = (const float*)d_in[12];  const float* b_fc1 = (const float*)d_in[13];
    const float* W_fc2 = (const float*)d_in[14];  const float* b_fc2 = (const float*)d_in[15];
    const float* W_flat = (const float*)d_in[16]; const float* b_flat = (const float*)d_in[17];
    const float* W_gc3 = (const float*)d_in[18];  const float* b_gc3 = (const float*)d_in[19];
    const float* W_gc4 = (const float*)d_in[20];  const float* b_gc4 = (const float*)d_in[21];

    float* out = (float*)d_out;
    float* out_deg = out;
    float* out_gen = out + OUT_GEN_OFF;
    float* out_nc  = out + OUT_NC_OFF;

    const long long nnz_adj = in_sizes[2];
    const int E = in_sizes[1] / 2;

    void* p;
    float *bufA, *bufB, *z, *c7;
    __half *g1h, *g2h, *fillh, *fhi, *flo, *hhi, *hlo, *znh;
    __half *wh_fc2, *wh_flat, *wh_gc3, *wh_fc1, *whi_gc1, *wlo_gc1, *whi_gc2, *wlo_gc2;
    int *pdeg, *cnt, *fill, *off_enc, *off_mend, *ecol, *mcol;
    float *eval;
    cudaGetSymbolAddress(&p, g_bufA);  bufA  = (float*)p;
    cudaGetSymbolAddress(&p, g_bufB);  bufB  = (float*)p;
    cudaGetSymbolAddress(&p, g_z);     z     = (float*)p;
    cudaGetSymbolAddress(&p, g_c7);    c7    = (float*)p;
    cudaGetSymbolAddress(&p, g_pdeg);  pdeg  = (int*)p;
    cudaGetSymbolAddress(&p, g_cnt);   cnt   = (int*)p;
    cudaGetSymbolAddress(&p, g_fill);  fill  = (int*)p;
    cudaGetSymbolAddress(&p, g_off_enc);  off_enc  = (int*)p;
    cudaGetSymbolAddress(&p, g_off_mend); off_mend = (int*)p;
    cudaGetSymbolAddress(&p, g_ecol);  ecol  = (int*)p;
    cudaGetSymbolAddress(&p, g_eval);  eval  = (float*)p;
    cudaGetSymbolAddress(&p, g_mcol);  mcol  = (int*)p;
    cudaGetSymbolAddress(&p, g_g1h);   g1h   = (__half*)p;
    cudaGetSymbolAddress(&p, g_g2h);   g2h   = (__half*)p;
    cudaGetSymbolAddress(&p, g_fillh); fillh = (__half*)p;
    cudaGetSymbolAddress(&p, g_fhi);   fhi   = (__half*)p;
    cudaGetSymbolAddress(&p, g_flo);   flo   = (__half*)p;
    cudaGetSymbolAddress(&p, g_hhi);   hhi   = (__half*)p;
    cudaGetSymbolAddress(&p, g_hlo);   hlo   = (__half*)p;
    cudaGetSymbolAddress(&p, g_znh);   znh   = (__half*)p;
    cudaGetSymbolAddress(&p, g_wh_fc2);  wh_fc2  = (__half*)p;
    cudaGetSymbolAddress(&p, g_wh_flat); wh_flat = (__half*)p;
    cudaGetSymbolAddress(&p, g_wh_gc3);  wh_gc3  = (__half*)p;
    cudaGetSymbolAddress(&p, g_wh_fc1);  wh_fc1  = (__half*)p;
    cudaGetSymbolAddress(&p, g_whi_gc1); whi_gc1 = (__half*)p;
    cudaGetSymbolAddress(&p, g_wlo_gc1); wlo_gc1 = (__half*)p;
    cudaGetSymbolAddress(&p, g_whi_gc2); whi_gc2 = (__half*)p;
    cudaGetSymbolAddress(&p, g_wlo_gc2); wlo_gc2 = (__half*)p;

    cudaFuncSetAttribute((const void*)hmma_gemm_kernel<0, 0>,
                         cudaFuncAttributeMaxDynamicSharedMemorySize, H_SMEM_TOTAL);
    cudaFuncSetAttribute((const void*)hmma_gemm_kernel<1, 1>,
                         cudaFuncAttributeMaxDynamicSharedMemorySize, H_SMEM_TOTAL);
    cudaFuncSetAttribute((const void*)hmma_gemm_kernel<2, 2>,
                         cudaFuncAttributeMaxDynamicSharedMemorySize, H_SMEM_TOTAL);
    cudaFuncSetAttribute((const void*)hmma_gemm3_kernel,
                         cudaFuncAttributeMaxDynamicSharedMemorySize, H_SMEM_TOTAL);

    const int TB = 256;
    dim3 tblk(32, 8);

    // 0) prep
    detect_idx_kernel<<<1, 32>>>(adj_rows);
    transpose_half_kernel<<<dim3(cdiv(256, 32), cdiv(2048, 32)), tblk>>>(W_fc2, wh_fc2, 256, 2048, 256, 2048);
    transpose_half_kernel<<<dim3(cdiv(2048, 32), cdiv(2560, 32)), tblk>>>(W_flat, wh_flat, 2048, 2500, 2048, 2560);
    transpose_half_kernel<<<dim3(cdiv(512, 32), cdiv(256, 32)), tblk>>>(W_gc3, wh_gc3, 500, 256, 512, 256);
    transpose_half_kernel<<<dim3(cdiv(128, 32), cdiv(256, 32)), tblk>>>(W_fc1, wh_fc1, 64, 256, 128, 256);
    transpose_half_split_kernel<<<dim3(cdiv(512, 32), cdiv(256, 32)), tblk>>>(W_gc1, whi_gc1, wlo_gc1, 500, 256, 512, 256);
    transpose_half_split_kernel<<<dim3(cdiv(256, 32), cdiv(128, 32)), tblk>>>(W_gc2, whi_gc2, wlo_gc2, 256, 64, 256, 128);
    feat_prep_kernel<<<cdiv((long long)NNODES * 512, TB), TB>>>(feat, fhi, flo, fillh);

    // 0b) encoder CSR build
    cudaMemsetAsync(cnt, 0, NNODES * sizeof(int));
    enc_hist_kernel<<<cdiv(nnz_adj, TB), TB>>>(adj_rows, nnz_adj);
    scan_kernel<<<1, 1024>>>(cnt, off_enc, fill, NNODES);
    enc_fill_kernel<<<cdiv(nnz_adj, TB), TB>>>(adj_rows, adj_cols, adj_vals, nnz_adj);

    // 1) XW1 = feat @ W_gc1 — fused split-3 fp16 (fp32-class)
    {
        dim3 grid(HID / 128, cdiv(NNODES, 128));
        hmma_gemm3_kernel<<<grid, 256, H_SMEM_TOTAL>>>(
            fhi, fhi, flo, whi_gc1, wlo_gc1, whi_gc1, bufA, NNODES, HID, 512, 512);
    }
    // 2) h = relu(spmm + b1) — CSR gather, split fp16 output
    spmm_gather_split_kernel<<<cdiv(NNODES, 8), TB>>>(off_enc, ecol, eval, bufA, b_gc1, hhi, hlo, NNODES);
    // 3) hW2 = h @ W_gc2 — fused split-3 fp16 (fp32-class)
    {
        dim3 grid(1, cdiv(NNODES, 128));
        hmma_gemm3_kernel<<<grid, 256, H_SMEM_TOTAL>>>(
            hhi, hhi, hlo, whi_gc2, wlo_gc2, whi_gc2, bufA, NNODES, LAT, 256, 256);
    }
    // 4) z = relu(spmm + b2)
    spmm_gather_kernel<64, false><<<cdiv(NNODES, 8), TB>>>(off_enc, ecol, eval, bufA, b_gc2, z, NNODES);
    // 5) degree + pred_deg
    degree_kernel<<<cdiv(NNODES, TB / 32), TB>>>(z, W_reg, b_reg, out_deg, pdeg, NNODES);
    // 5b) mend CSR build
    cudaMemsetAsync(cnt, 0, NODE_LEN * sizeof(int));
    mend_hist_edges_kernel<<<cdiv(E, TB), TB>>>(edges, E);
    mend_hist_new_kernel<<<cdiv(NNODES * NPRED, TB), TB>>>(pdeg);
    scan_kernel<<<1, 1024>>>(cnt, off_mend, fill, NODE_LEN);
    mend_fill_edges_kernel<<<cdiv(E, TB), TB>>>(edges, E);
    mend_fill_new_kernel<<<cdiv(NNODES * NPRED, TB), TB>>>(pdeg);
    // 6) znh = half(z + noise), zero-padded to K=128
    add_half_pad_kernel<<<cdiv((long long)NNODES * 128, TB), TB>>>(znh, z, noise);
    // 7) g1h = half(relu(znh @ W_fc1 + b)) — fp16 mma (K=128 padded)
    {
        dim3 grid(FC1N / 128, cdiv(NNODES, 128));
        hmma_gemm_kernel<1, 1><<<grid, 256, H_SMEM_TOTAL>>>(
            znh, wh_fc1, b_fc1, nullptr, g1h, NNODES, FC1N, 128, 128);
    }
    // 8) g2h = half(relu(g1h @ W_fc2 + b)) — fp16 mma
    {
        dim3 grid(FC2N / 128, cdiv(NNODES, 128));
        hmma_gemm_kernel<1, 1><<<grid, 256, H_SMEM_TOTAL>>>(
            g1h, wh_fc2, b_fc2, nullptr, g2h, NNODES, FC2N, FC1N, 256);
    }
    // 9) gen_feat = tanh(g2h @ W_flat + b) — fp16 mma; f32 out_gen + half fillh gen rows
    {
        dim3 grid(2560 / 128, cdiv(NNODES, 128));
        hmma_gemm_kernel<2, 2><<<grid, 256, H_SMEM_TOTAL>>>(
            g2h, wh_flat, b_flat, out_gen, fillh, NNODES, GENF, FC2N, 2048);
    }
    // 10) fillW3 = fillh @ W_gc3 — fp16 mma (K padded to 512)
    {
        dim3 grid(HID / 128, cdiv(NODE_LEN, 128));
        hmma_gemm_kernel<0, 0><<<grid, 256, H_SMEM_TOTAL>>>(
            fillh, wh_gc3, nullptr, bufA, nullptr, NODE_LEN, HID, 512, 512);
    }
    // 12) mend layer 1 — CSR gather, fused normalize+bias+relu
    spmm_gather_kernel<256, true><<<cdiv(NODE_LEN, 8), TB>>>(off_mend, mcol, nullptr, bufA, b_gc3, bufB, NODE_LEN);
    // 13) c7 = h2 @ W_gc4 — skinny N=16
    skinny16_kernel<<<cdiv(NODE_LEN, 128), 128>>>(bufB, W_gc4, c7, NODE_LEN);
    // 14) mend layer 2 — CSR gather
    spmm_gather_kernel<16, true><<<cdiv(NODE_LEN, 8), TB>>>(off_mend, mcol, nullptr, c7, b_gc4, out_nc, NODE_LEN);

    (void)n_in; (void)out_size;
}